// round 9
// baseline (speedup 1.0000x reference)
#include <cuda_runtime.h>
#include <cuda_bf16.h>
#include <cstdint>

#define H_HEADS 16
#define DHEAD   64
#define RMS_EPS 1.1920928955078125e-07f
#define MAXTOK  4096
#define LOG2E   1.4426950408889634f
#define FIXMAX  12.0f   // exp2-domain scores bounded by 8*log2e = 11.54

// ---------------- scratch ----------------
__device__ __nv_bfloat16 g_ahi [MAXTOK * 1024];
__device__ __nv_bfloat16 g_alo [MAXTOK * 1024];
__device__ __nv_bfloat16 g_bhi [1024 * 1024];
__device__ __nv_bfloat16 g_blo [1024 * 1024];
__device__ __nv_bfloat16 g_qhi [MAXTOK * 1024];
__device__ __nv_bfloat16 g_qlo [MAXTOK * 1024];
__device__ __nv_bfloat16 g_kvhi[MAXTOK * 1024];
__device__ __nv_bfloat16 g_kvlo[MAXTOK * 1024];

// ---------------- helpers ----------------
__device__ __forceinline__ uint32_t smem_u32(const void* p) {
    uint32_t a;
    asm("{ .reg .u64 t; cvta.to.shared.u64 t, %1; cvt.u32.u64 %0, t; }" : "=r"(a) : "l"(p));
    return a;
}

#define LDSM_X4(r0, r1, r2, r3, addr) \
    asm volatile("ldmatrix.sync.aligned.m8n8.x4.shared.b16 {%0,%1,%2,%3}, [%4];" \
                 : "=r"(r0), "=r"(r1), "=r"(r2), "=r"(r3) : "r"(addr))

#define LDSM_X4_T(r0, r1, r2, r3, addr) \
    asm volatile("ldmatrix.sync.aligned.m8n8.x4.trans.shared.b16 {%0,%1,%2,%3}, [%4];" \
                 : "=r"(r0), "=r"(r1), "=r"(r2), "=r"(r3) : "r"(addr))

#define MMA_BF16(c0, c1, c2, c3, a0, a1, a2, a3, b0, b1) \
    asm volatile("mma.sync.aligned.m16n8k16.row.col.f32.bf16.bf16.f32 " \
                 "{%0,%1,%2,%3}, {%4,%5,%6,%7}, {%8,%9}, {%0,%1,%2,%3};" \
                 : "+f"(c0), "+f"(c1), "+f"(c2), "+f"(c3) \
                 : "r"(a0), "r"(a1), "r"(a2), "r"(a3), "r"(b0), "r"(b1))

#define CP16(saddr, gptr) \
    asm volatile("cp.async.cg.shared.global [%0], [%1], 16;" :: "r"(saddr), "l"(gptr))
#define CP_COMMIT() asm volatile("cp.async.commit_group;" ::: "memory")
#define CP_WAIT1()  asm volatile("cp.async.wait_group 1;" ::: "memory")
#define CP_WAIT0()  asm volatile("cp.async.wait_group 0;" ::: "memory")

__device__ __forceinline__ uint32_t pack_bf2(__nv_bfloat16 a, __nv_bfloat16 b) {
    __nv_bfloat162 t(a, b);
    return *(uint32_t*)&t;
}
__device__ __forceinline__ void split_pack(float x, float y, uint32_t& hi, uint32_t& lo) {
    __nv_bfloat16 hx = __float2bfloat16(x), hy = __float2bfloat16(y);
    __nv_bfloat16 lx = __float2bfloat16(x - __bfloat162float(hx));
    __nv_bfloat16 ly = __float2bfloat16(y - __bfloat162float(hy));
    hi = pack_bf2(hx, hy);
    lo = pack_bf2(lx, ly);
}

// ---------------------------------------------------------------------------
// split fp32 -> bf16 hi + bf16 lo (weights)
// ---------------------------------------------------------------------------
__global__ __launch_bounds__(256) void split_bf16(
    const float* __restrict__ in, __nv_bfloat16* __restrict__ hi,
    __nv_bfloat16* __restrict__ lo, int n4)
{
    int i = blockIdx.x * blockDim.x + threadIdx.x;
    if (i >= n4) return;
    float4 v = ((const float4*)in)[i];
    uint32_t h0, l0, h1, l1;
    split_pack(v.x, v.y, h0, l0);
    split_pack(v.z, v.w, h1, l1);
    ((uint32_t*)hi)[2 * i]     = h0;
    ((uint32_t*)hi)[2 * i + 1] = h1;
    ((uint32_t*)lo)[2 * i]     = l0;
    ((uint32_t*)lo)[2 * i + 1] = l1;
}

// ---------------------------------------------------------------------------
// prep_q: x -> raw split [M,C] + roped/rms/scaled q split [B,H,T,D]
// ---------------------------------------------------------------------------
__global__ __launch_bounds__(256) void prep_q(
    const float* __restrict__ x, const float* __restrict__ cosb,
    const float* __restrict__ sinb,
    __nv_bfloat16* __restrict__ ahi, __nv_bfloat16* __restrict__ alo,
    __nv_bfloat16* __restrict__ qhi, __nv_bfloat16* __restrict__ qlo,
    float qscale, int T, int total_heads)
{
    int w = blockIdx.x * 8 + (threadIdx.x >> 5);
    if (w >= total_heads) return;
    int lane = threadIdx.x & 31;
    int h = w % H_HEADS;
    int t = (w / H_HEADS) % T;
    int b = w / (H_HEADS * T);

    size_t ibase = (size_t)w * DHEAD;
    float x1 = x[ibase + lane];
    float x2 = x[ibase + 32 + lane];

    {
        __nv_bfloat16 h1 = __float2bfloat16(x1);
        __nv_bfloat16 h2 = __float2bfloat16(x2);
        ahi[ibase + lane]      = h1;
        ahi[ibase + 32 + lane] = h2;
        alo[ibase + lane]      = __float2bfloat16(x1 - __bfloat162float(h1));
        alo[ibase + 32 + lane] = __float2bfloat16(x2 - __bfloat162float(h2));
    }

    float c  = cosb[t * 32 + lane];
    float s  = sinb[t * 32 + lane];
    float o1 = x1 * c + x2 * s;
    float o2 = -x1 * s + x2 * c;

    float ss = o1 * o1 + o2 * o2;
#pragma unroll
    for (int off = 16; off; off >>= 1)
        ss += __shfl_xor_sync(0xffffffffu, ss, off);
    float r = rsqrtf(ss * (1.0f / 64.0f) + RMS_EPS) * qscale;

    o1 *= r; o2 *= r;
    __nv_bfloat16 h1 = __float2bfloat16(o1);
    __nv_bfloat16 h2 = __float2bfloat16(o2);
    size_t obase = ((size_t)(b * H_HEADS + h) * T + t) * DHEAD;
    qhi[obase + lane]      = h1;
    qhi[obase + 32 + lane] = h2;
    qlo[obase + lane]      = __float2bfloat16(o1 - __bfloat162float(h1));
    qlo[obase + 32 + lane] = __float2bfloat16(o2 - __bfloat162float(h2));
}

// ---------------------------------------------------------------------------
// cp.async double-buffered split-precision NT GEMM (unchanged)
// ---------------------------------------------------------------------------
#define KCH2   32
#define ROWB2  80
#define MATB2  (128 * ROWB2)
#define STB2   (4 * MATB2)
#define GEMM_SMEM (2 * STB2)

template <bool FUSE_ROPE>
__global__ __launch_bounds__(256) void gemm_mma(
    const __nv_bfloat16* __restrict__ Ahi, const __nv_bfloat16* __restrict__ Alo,
    const __nv_bfloat16* __restrict__ Bhi, const __nv_bfloat16* __restrict__ Blo,
    float* __restrict__ C,
    const float* __restrict__ cosb, const float* __restrict__ sinb,
    __nv_bfloat16* __restrict__ Ohi, __nv_bfloat16* __restrict__ Olo,
    int M, int N, int K, int T)
{
    extern __shared__ char smem[];
    const uint32_t sb = smem_u32(smem);

    const int tid  = threadIdx.x;
    const int wid  = tid >> 5;
    const int lane = tid & 31;
    const int m0 = blockIdx.y * 128, n0 = blockIdx.x * 128;

    const int wm = (wid & 3) * 32;
    const int wn = (wid >> 2) * 64;

    const int a_row = (lane & 7) + (lane & 8);
    const int a_col = (lane >> 4) * 16;
    const int b_row = (lane & 7) + ((lane >> 4) & 1) * 8;
    const int b_col = ((lane >> 3) & 1) * 16;

    const int grow = tid >> 1;
    const uint32_t s_off = (uint32_t)grow * ROWB2 + (tid & 1) * 32;
    const int gelem = (tid & 1) * 16;

    const __nv_bfloat16* gAh = Ahi + (size_t)(m0 + grow) * K + gelem;
    const __nv_bfloat16* gAl = Alo + (size_t)(m0 + grow) * K + gelem;
    const __nv_bfloat16* gBh = Bhi + (size_t)(n0 + grow) * K + gelem;
    const __nv_bfloat16* gBl = Blo + (size_t)(n0 + grow) * K + gelem;

    float c[2][8][4];
#pragma unroll
    for (int i = 0; i < 2; i++)
#pragma unroll
        for (int j = 0; j < 8; j++)
#pragma unroll
            for (int e = 0; e < 4; e++) c[i][j][e] = 0.f;

    const int nchunk = K / KCH2;

    auto fill = [&](int stage, int ch) {
        const int k0 = ch * KCH2;
        uint32_t s0 = sb + stage * STB2 + s_off;
        const __nv_bfloat16* a0 = gAh + k0;
        const __nv_bfloat16* a1 = gAl + k0;
        const __nv_bfloat16* b0 = gBh + k0;
        const __nv_bfloat16* b1 = gBl + k0;
        CP16(s0,                 a0);      CP16(s0 + 16,                 a0 + 8);
        CP16(s0 + MATB2,         a1);      CP16(s0 + MATB2 + 16,         a1 + 8);
        CP16(s0 + 2 * MATB2,     b0);      CP16(s0 + 2 * MATB2 + 16,     b0 + 8);
        CP16(s0 + 3 * MATB2,     b1);      CP16(s0 + 3 * MATB2 + 16,     b1 + 8);
    };

    fill(0, 0);
    CP_COMMIT();

    for (int ch = 0; ch < nchunk; ch++) {
        const int st = ch & 1;
        if (ch + 1 < nchunk) { fill(st ^ 1, ch + 1); CP_COMMIT(); CP_WAIT1(); }
        else                 { CP_WAIT0(); }
        __syncthreads();

        const uint32_t base = sb + st * STB2;
        const uint32_t sAhi = base, sBhi = base + 2 * MATB2;

#pragma unroll
        for (int ks = 0; ks < 2; ks++) {
            const int kb = ks * 32;
            uint32_t ah[2][4], al[2][4], bh[4][4], bl[4][4];
#pragma unroll
            for (int mi = 0; mi < 2; mi++) {
                uint32_t addr = sAhi + (uint32_t)(wm + mi * 16 + a_row) * ROWB2 + kb + a_col;
                LDSM_X4(ah[mi][0], ah[mi][1], ah[mi][2], ah[mi][3], addr);
                addr += MATB2;
                LDSM_X4(al[mi][0], al[mi][1], al[mi][2], al[mi][3], addr);
            }
#pragma unroll
            for (int nb = 0; nb < 4; nb++) {
                uint32_t addr = sBhi + (uint32_t)(wn + nb * 16 + b_row) * ROWB2 + kb + b_col;
                LDSM_X4(bh[nb][0], bh[nb][1], bh[nb][2], bh[nb][3], addr);
                addr += MATB2;
                LDSM_X4(bl[nb][0], bl[nb][1], bl[nb][2], bl[nb][3], addr);
            }
#pragma unroll
            for (int mi = 0; mi < 2; mi++)
#pragma unroll
                for (int nb = 0; nb < 4; nb++)
#pragma unroll
                    for (int sj = 0; sj < 2; sj++) {
                        float* cc = c[mi][nb * 2 + sj];
                        MMA_BF16(cc[0], cc[1], cc[2], cc[3],
                                 ah[mi][0], ah[mi][1], ah[mi][2], ah[mi][3],
                                 bh[nb][sj * 2], bh[nb][sj * 2 + 1]);
                        MMA_BF16(cc[0], cc[1], cc[2], cc[3],
                                 ah[mi][0], ah[mi][1], ah[mi][2], ah[mi][3],
                                 bl[nb][sj * 2], bl[nb][sj * 2 + 1]);
                        MMA_BF16(cc[0], cc[1], cc[2], cc[3],
                                 al[mi][0], al[mi][1], al[mi][2], al[mi][3],
                                 bh[nb][sj * 2], bh[nb][sj * 2 + 1]);
                    }
        }
        __syncthreads();
    }

    const int g  = lane >> 2;
    const int t2 = (lane & 3) * 2;

    if (!FUSE_ROPE) {
#pragma unroll
        for (int mi = 0; mi < 2; mi++) {
            float* r0 = C + (size_t)(m0 + wm + mi * 16 + g) * N + n0 + wn + t2;
            float* r1 = r0 + 8 * N;
#pragma unroll
            for (int nj = 0; nj < 8; nj++) {
                *(float2*)(r0 + nj * 8) = make_float2(c[mi][nj][0], c[mi][nj][1]);
                *(float2*)(r1 + nj * 8) = make_float2(c[mi][nj][2], c[mi][nj][3]);
            }
        }
    } else {
        const int h = (n0 + wn) >> 6;
#pragma unroll
        for (int mi = 0; mi < 2; mi++) {
#pragma unroll
            for (int half = 0; half < 2; half++) {
                const int m = m0 + wm + mi * 16 + g + half * 8;
                const int b = m / T, t = m % T;
                float o1[4][2], o2[4][2];
                float ss = 0.f;
#pragma unroll
                for (int nj = 0; nj < 4; nj++) {
#pragma unroll
                    for (int e = 0; e < 2; e++) {
                        const int d = nj * 8 + t2 + e;
                        float x1 = c[mi][nj][half * 2 + e];
                        float x2 = c[mi][nj + 4][half * 2 + e];
                        float co = cosb[t * 32 + d];
                        float si = sinb[t * 32 + d];
                        float a = x1 * co + x2 * si;
                        float bb = -x1 * si + x2 * co;
                        o1[nj][e] = a; o2[nj][e] = bb;
                        ss += a * a + bb * bb;
                    }
                }
                ss += __shfl_xor_sync(0xffffffffu, ss, 1);
                ss += __shfl_xor_sync(0xffffffffu, ss, 2);
                float r = rsqrtf(ss * (1.0f / 64.0f) + RMS_EPS);
                const size_t ob = ((size_t)(b * H_HEADS + h) * T + t) * DHEAD + t2;
#pragma unroll
                for (int nj = 0; nj < 4; nj++) {
                    uint32_t hi, lo;
                    split_pack(o1[nj][0] * r, o1[nj][1] * r, hi, lo);
                    *(uint32_t*)(Ohi + ob + nj * 8) = hi;
                    *(uint32_t*)(Olo + ob + nj * 8) = lo;
                    split_pack(o2[nj][0] * r, o2[nj][1] * r, hi, lo);
                    *(uint32_t*)(Ohi + ob + 32 + nj * 8) = hi;
                    *(uint32_t*)(Olo + ob + 32 + nj * 8) = lo;
                }
            }
        }
    }
}

// ---------------------------------------------------------------------------
// Chunk-streamed sliding-window attention, 128-row Q tile (2 m-frags/warp).
// Fragment loads amortized over 2x MMAs; fixed-max linear softmax.
// ---------------------------------------------------------------------------
#define ATT_ROWB 144
#define ATT_MAT  (64 * ATT_ROWB)

__global__ __launch_bounds__(128) void attn_mma(
    const __nv_bfloat16* __restrict__ Qhi, const __nv_bfloat16* __restrict__ Qlo,
    const __nv_bfloat16* __restrict__ KVhi, const __nv_bfloat16* __restrict__ KVlo,
    __nv_bfloat16* __restrict__ Ohi, __nv_bfloat16* __restrict__ Olo,
    const int* __restrict__ wl, int T)
{
    __shared__ char smc[2 * ATT_MAT];
    const uint32_t sKhi = smem_u32(smc);

    const int tid = threadIdx.x, wid = tid >> 5, lane = tid & 31;
    const int qt = blockIdx.x, h = blockIdx.y, b = blockIdx.z;
    const int q0 = qt * 128;
    const int W = *wl;
    const size_t hb = (size_t)(b * H_HEADS + h) * T * DHEAD;

    const int lrow = tid >> 1;
    const uint32_t s_off = (uint32_t)lrow * ATT_ROWB + (tid & 1) * 64;
    const int gcol = (tid & 1) * 32;

    const int a_row  = (lane & 7) + (lane & 8);
    const int a_colB = (lane >> 4) * 16;
    const int b_row  = (lane & 7) + ((lane >> 4) & 1) * 8;
    const int b_colB = ((lane >> 3) & 1) * 16;
    const int t_m = lane >> 3, t_r = lane & 7;

    // ---- stage Q halves through the KV buffer -> fragments ----
    // warp's rows: mi*64 + wid*16 + (0..15)
    uint32_t qh[2][4][4], ql[2][4][4];
#pragma unroll
    for (int mi = 0; mi < 2; mi++) {
        __syncthreads();
        {
            const uint4* sh = (const uint4*)(Qhi + hb + (size_t)(q0 + mi * 64 + lrow) * DHEAD + gcol);
            const uint4* sl = (const uint4*)(Qlo + hb + (size_t)(q0 + mi * 64 + lrow) * DHEAD + gcol);
#pragma unroll
            for (int j = 0; j < 4; j++) {
                *(uint4*)(smc + (s_off + j * 16)) = sh[j];
                *(uint4*)(smc + ATT_MAT + (s_off + j * 16)) = sl[j];
            }
        }
        __syncthreads();
#pragma unroll
        for (int kc = 0; kc < 4; kc++) {
            uint32_t ad = sKhi + (uint32_t)(wid * 16 + a_row) * ATT_ROWB + kc * 32 + a_colB;
            LDSM_X4(qh[mi][kc][0], qh[mi][kc][1], qh[mi][kc][2], qh[mi][kc][3], ad);
            LDSM_X4(ql[mi][kc][0], ql[mi][kc][1], ql[mi][kc][2], ql[mi][kc][3], ad + ATT_MAT);
        }
    }

    float o[2][8][4];
#pragma unroll
    for (int mi = 0; mi < 2; mi++)
#pragma unroll
        for (int i = 0; i < 8; i++)
#pragma unroll
            for (int e = 0; e < 4; e++) o[mi][i][e] = 0.f;
    float lsum[2][2] = {{0.f, 0.f}, {0.f, 0.f}};

    int lo_t = q0 - W; if (lo_t < 0) lo_t = 0;
    const int kt_lo = lo_t >> 6;
    const int kt_hi = (q0 + 127) >> 6;

    for (int kt = kt_lo; kt <= kt_hi; kt++) {
        const int k0 = kt * 64;
        __syncthreads();
        {
            const uint4* sh = (const uint4*)(KVhi + hb + (size_t)(k0 + lrow) * DHEAD + gcol);
            const uint4* sl = (const uint4*)(KVlo + hb + (size_t)(k0 + lrow) * DHEAD + gcol);
#pragma unroll
            for (int j = 0; j < 4; j++) {
                *(uint4*)(smc + (s_off + j * 16)) = sh[j];
                *(uint4*)(smc + ATT_MAT + (s_off + j * 16)) = sl[j];
            }
        }
        __syncthreads();

        const bool fullt = (k0 + 63 <= q0) && (q0 + 127 - k0 <= W);

#pragma unroll
        for (int n16 = 0; n16 < 4; n16++) {
            // ---- S chunk: both m-fragments x 16 keys ----
            float s[2][2][4];
#pragma unroll
            for (int mi = 0; mi < 2; mi++)
#pragma unroll
                for (int sj = 0; sj < 2; sj++)
#pragma unroll
                    for (int e = 0; e < 4; e++) s[mi][sj][e] = 0.f;

#pragma unroll
            for (int kc = 0; kc < 4; kc++) {
                uint32_t bh[4], bl[4];
                uint32_t ad = sKhi + (uint32_t)(n16 * 16 + b_row) * ATT_ROWB + kc * 32 + b_colB;
                LDSM_X4(bh[0], bh[1], bh[2], bh[3], ad);
                LDSM_X4(bl[0], bl[1], bl[2], bl[3], ad + ATT_MAT);
#pragma unroll
                for (int mi = 0; mi < 2; mi++)
#pragma unroll
                    for (int sj = 0; sj < 2; sj++) {
                        float* cc = s[mi][sj];
                        MMA_BF16(cc[0], cc[1], cc[2], cc[3],
                                 qh[mi][kc][0], qh[mi][kc][1], qh[mi][kc][2], qh[mi][kc][3],
                                 bh[sj * 2], bh[sj * 2 + 1]);
                        MMA_BF16(cc[0], cc[1], cc[2], cc[3],
                                 qh[mi][kc][0], qh[mi][kc][1], qh[mi][kc][2], qh[mi][kc][3],
                                 bl[sj * 2], bl[sj * 2 + 1]);
                        MMA_BF16(cc[0], cc[1], cc[2], cc[3],
                                 ql[mi][kc][0], ql[mi][kc][1], ql[mi][kc][2], ql[mi][kc][3],
                                 bh[sj * 2], bh[sj * 2 + 1]);
                    }
            }

            if (!fullt) {
#pragma unroll
                for (int mi = 0; mi < 2; mi++) {
                    const int qr = q0 + mi * 64 + wid * 16 + (lane >> 2);
#pragma unroll
                    for (int sj = 0; sj < 2; sj++) {
                        const int kb = k0 + (n16 * 2 + sj) * 8 + (lane & 3) * 2;
#pragma unroll
                        for (int e = 0; e < 4; e++) {
                            int qq = qr + ((e >= 2) ? 8 : 0);
                            int kk = kb + (e & 1);
                            if (kk > qq || qq - kk > W) s[mi][sj][e] = -1e30f;
                        }
                    }
                }
            }

            // ---- exp2 + partial sums + pack, then PV chunk ----
            uint32_t ph[2][4], pl[2][4];
#pragma unroll
            for (int mi = 0; mi < 2; mi++) {
#pragma unroll
                for (int sj = 0; sj < 2; sj++)
#pragma unroll
                    for (int e = 0; e < 4; e++) {
                        float p = exp2f(s[mi][sj][e] - FIXMAX);
                        s[mi][sj][e] = p;
                        lsum[mi][e >> 1] += p;
                    }
                split_pack(s[mi][0][0], s[mi][0][1], ph[mi][0], pl[mi][0]);
                split_pack(s[mi][0][2], s[mi][0][3], ph[mi][1], pl[mi][1]);
                split_pack(s[mi][1][0], s[mi][1][1], ph[mi][2], pl[mi][2]);
                split_pack(s[mi][1][2], s[mi][1][3], ph[mi][3], pl[mi][3]);
            }

#pragma unroll
            for (int dg = 0; dg < 4; dg++) {
                uint32_t vh[4], vl[4];
                uint32_t ad = sKhi + (uint32_t)(n16 * 16 + t_r + (t_m & 1) * 8) * ATT_ROWB
                            + dg * 32 + (t_m >> 1) * 16;
                LDSM_X4_T(vh[0], vh[1], vh[2], vh[3], ad);
                LDSM_X4_T(vl[0], vl[1], vl[2], vl[3], ad + ATT_MAT);
#pragma unroll
                for (int mi = 0; mi < 2; mi++)
#pragma unroll
                    for (int sj = 0; sj < 2; sj++) {
                        float* cc = o[mi][dg * 2 + sj];
                        MMA_BF16(cc[0], cc[1], cc[2], cc[3],
                                 ph[mi][0], ph[mi][1], ph[mi][2], ph[mi][3],
                                 vh[sj * 2], vh[sj * 2 + 1]);
                        MMA_BF16(cc[0], cc[1], cc[2], cc[3],
                                 pl[mi][0], pl[mi][1], pl[mi][2], pl[mi][3],
                                 vh[sj * 2], vh[sj * 2 + 1]);
                        MMA_BF16(cc[0], cc[1], cc[2], cc[3],
                                 ph[mi][0], ph[mi][1], ph[mi][2], ph[mi][3],
                                 vl[sj * 2], vl[sj * 2 + 1]);
                    }
            }
        }
    }

    // ---- epilogue ----
    const int g = lane >> 2, t2 = (lane & 3) * 2;
#pragma unroll
    for (int mi = 0; mi < 2; mi++) {
        float s0 = lsum[mi][0], s1 = lsum[mi][1];
        s0 += __shfl_xor_sync(0xffffffffu, s0, 1);
        s0 += __shfl_xor_sync(0xffffffffu, s0, 2);
        s1 += __shfl_xor_sync(0xffffffffu, s1, 1);
        s1 += __shfl_xor_sync(0xffffffffu, s1, 2);
        const float inv0 = 1.f / s0;
        const float inv1 = 1.f / s1;
        const size_t r0 = (size_t)(b * T + q0 + mi * 64 + wid * 16 + g) * 1024 + h * 64 + t2;
        const size_t r1 = r0 + (size_t)8 * 1024;
#pragma unroll
        for (int nj = 0; nj < 8; nj++) {
            uint32_t hi, lo;
            split_pack(o[mi][nj][0] * inv0, o[mi][nj][1] * inv0, hi, lo);
            *(uint32_t*)(Ohi + r0 + nj * 8) = hi;
            *(uint32_t*)(Olo + r0 + nj * 8) = lo;
            split_pack(o[mi][nj][2] * inv1, o[mi][nj][3] * inv1, hi, lo);
            *(uint32_t*)(Ohi + r1 + nj * 8) = hi;
            *(uint32_t*)(Olo + r1 + nj * 8) = lo;
        }
    }
}

// ---------------------------------------------------------------------------
extern "C" void kernel_launch(void* const* d_in, const int* in_sizes, int n_in,
                              void* d_out, int out_size)
{
    const float* x      = (const float*)d_in[0];
    const float* cosb   = (const float*)d_in[1];
    const float* sinb   = (const float*)d_in[2];
    const float* kv_w   = (const float*)d_in[3];
    const float* proj_w = (const float*)d_in[4];
    const int* wl       = (n_in >= 6) ? (const int*)d_in[5] : nullptr;

    const int T = in_sizes[1] / 32;
    const int C = 1024;
    const int B = in_sizes[0] / (T * C);
    const int M = B * T;
    const int total_heads = M * H_HEADS;

    __nv_bfloat16 *ahi, *alo, *bhi, *blo, *qhi, *qlo, *kvhi, *kvlo;
    cudaGetSymbolAddress((void**)&ahi,  g_ahi);
    cudaGetSymbolAddress((void**)&alo,  g_alo);
    cudaGetSymbolAddress((void**)&bhi,  g_bhi);
    cudaGetSymbolAddress((void**)&blo,  g_blo);
    cudaGetSymbolAddress((void**)&qhi,  g_qhi);
    cudaGetSymbolAddress((void**)&qlo,  g_qlo);
    cudaGetSymbolAddress((void**)&kvhi, g_kvhi);
    cudaGetSymbolAddress((void**)&kvlo, g_kvlo);

    cudaFuncSetAttribute(gemm_mma<true>,  cudaFuncAttributeMaxDynamicSharedMemorySize, GEMM_SMEM);
    cudaFuncSetAttribute(gemm_mma<false>, cudaFuncAttributeMaxDynamicSharedMemorySize, GEMM_SMEM);

    {
        int blocks = (total_heads + 7) / 8;
        prep_q<<<blocks, 256>>>(x, cosb, sinb, ahi, alo, qhi, qlo,
                                0.125f * LOG2E, T, total_heads);
    }
    split_bf16<<<(C * C / 4 + 255) / 256, 256>>>(kv_w, bhi, blo, C * C / 4);
    {
        dim3 grid(C / 128, M / 128);
        gemm_mma<true><<<grid, 256, GEMM_SMEM>>>(ahi, alo, bhi, blo, nullptr,
                                                 cosb, sinb, kvhi, kvlo, M, C, C, T);
    }
    {
        dim3 grid(T / 128, H_HEADS, B);
        attn_mma<<<grid, 128>>>(qhi, qlo, kvhi, kvlo, ahi, alo, wl, T);
    }
    split_bf16<<<(C * C / 4 + 255) / 256, 256>>>(proj_w, bhi, blo, C * C / 4);
    {
        dim3 grid(C / 128, M / 128);
        gemm_mma<false><<<grid, 256, GEMM_SMEM>>>(ahi, alo, bhi, blo, (float*)d_out,
                                                  nullptr, nullptr, nullptr, nullptr, M, C, C, T);
    }
}

// round 10
// speedup vs baseline: 1.0681x; 1.0681x over previous
#include <cuda_runtime.h>
#include <cuda_bf16.h>
#include <cstdint>

#define H_HEADS 16
#define DHEAD   64
#define RMS_EPS 1.1920928955078125e-07f
#define MAXTOK  4096
#define LOG2E   1.4426950408889634f
#define FIXMAX  12.0f

// ---------------- scratch ----------------
__device__ __nv_bfloat16 g_ahi [MAXTOK * 1024];
__device__ __nv_bfloat16 g_alo [MAXTOK * 1024];
__device__ __nv_bfloat16 g_bhi [1024 * 1024];
__device__ __nv_bfloat16 g_blo [1024 * 1024];
__device__ __nv_bfloat16 g_qhi [MAXTOK * 1024];
__device__ __nv_bfloat16 g_qlo [MAXTOK * 1024];
__device__ __nv_bfloat16 g_kvhi[MAXTOK * 1024];
__device__ __nv_bfloat16 g_kvlo[MAXTOK * 1024];

// ---------------- helpers ----------------
__device__ __forceinline__ uint32_t smem_u32(const void* p) {
    uint32_t a;
    asm("{ .reg .u64 t; cvta.to.shared.u64 t, %1; cvt.u32.u64 %0, t; }" : "=r"(a) : "l"(p));
    return a;
}

#define LDSM_X4(r0, r1, r2, r3, addr) \
    asm volatile("ldmatrix.sync.aligned.m8n8.x4.shared.b16 {%0,%1,%2,%3}, [%4];" \
                 : "=r"(r0), "=r"(r1), "=r"(r2), "=r"(r3) : "r"(addr))

#define LDSM_X4_T(r0, r1, r2, r3, addr) \
    asm volatile("ldmatrix.sync.aligned.m8n8.x4.trans.shared.b16 {%0,%1,%2,%3}, [%4];" \
                 : "=r"(r0), "=r"(r1), "=r"(r2), "=r"(r3) : "r"(addr))

#define MMA_BF16(c0, c1, c2, c3, a0, a1, a2, a3, b0, b1) \
    asm volatile("mma.sync.aligned.m16n8k16.row.col.f32.bf16.bf16.f32 " \
                 "{%0,%1,%2,%3}, {%4,%5,%6,%7}, {%8,%9}, {%0,%1,%2,%3};" \
                 : "+f"(c0), "+f"(c1), "+f"(c2), "+f"(c3) \
                 : "r"(a0), "r"(a1), "r"(a2), "r"(a3), "r"(b0), "r"(b1))

#define CP16(saddr, gptr) \
    asm volatile("cp.async.cg.shared.global [%0], [%1], 16;" :: "r"(saddr), "l"(gptr))
#define CP_COMMIT() asm volatile("cp.async.commit_group;" ::: "memory")
#define CP_WAIT1()  asm volatile("cp.async.wait_group 1;" ::: "memory")
#define CP_WAIT0()  asm volatile("cp.async.wait_group 0;" ::: "memory")

__device__ __forceinline__ uint32_t pack_bf2(__nv_bfloat16 a, __nv_bfloat16 b) {
    __nv_bfloat162 t(a, b);
    return *(uint32_t*)&t;
}
__device__ __forceinline__ void split_pack(float x, float y, uint32_t& hi, uint32_t& lo) {
    __nv_bfloat16 hx = __float2bfloat16(x), hy = __float2bfloat16(y);
    __nv_bfloat16 lx = __float2bfloat16(x - __bfloat162float(hx));
    __nv_bfloat16 ly = __float2bfloat16(y - __bfloat162float(hy));
    hi = pack_bf2(hx, hy);
    lo = pack_bf2(lx, ly);
}

// ---------------------------------------------------------------------------
__global__ __launch_bounds__(256) void split_bf16(
    const float* __restrict__ in, __nv_bfloat16* __restrict__ hi,
    __nv_bfloat16* __restrict__ lo, int n4)
{
    int i = blockIdx.x * blockDim.x + threadIdx.x;
    if (i >= n4) return;
    float4 v = ((const float4*)in)[i];
    uint32_t h0, l0, h1, l1;
    split_pack(v.x, v.y, h0, l0);
    split_pack(v.z, v.w, h1, l1);
    ((uint32_t*)hi)[2 * i]     = h0;
    ((uint32_t*)hi)[2 * i + 1] = h1;
    ((uint32_t*)lo)[2 * i]     = l0;
    ((uint32_t*)lo)[2 * i + 1] = l1;
}

// ---------------------------------------------------------------------------
__global__ __launch_bounds__(256) void prep_q(
    const float* __restrict__ x, const float* __restrict__ cosb,
    const float* __restrict__ sinb,
    __nv_bfloat16* __restrict__ ahi, __nv_bfloat16* __restrict__ alo,
    __nv_bfloat16* __restrict__ qhi, __nv_bfloat16* __restrict__ qlo,
    float qscale, int T, int total_heads)
{
    int w = blockIdx.x * 8 + (threadIdx.x >> 5);
    if (w >= total_heads) return;
    int lane = threadIdx.x & 31;
    int h = w % H_HEADS;
    int t = (w / H_HEADS) % T;
    int b = w / (H_HEADS * T);

    size_t ibase = (size_t)w * DHEAD;
    float x1 = x[ibase + lane];
    float x2 = x[ibase + 32 + lane];

    {
        __nv_bfloat16 h1 = __float2bfloat16(x1);
        __nv_bfloat16 h2 = __float2bfloat16(x2);
        ahi[ibase + lane]      = h1;
        ahi[ibase + 32 + lane] = h2;
        alo[ibase + lane]      = __float2bfloat16(x1 - __bfloat162float(h1));
        alo[ibase + 32 + lane] = __float2bfloat16(x2 - __bfloat162float(h2));
    }

    float c  = cosb[t * 32 + lane];
    float s  = sinb[t * 32 + lane];
    float o1 = x1 * c + x2 * s;
    float o2 = -x1 * s + x2 * c;

    float ss = o1 * o1 + o2 * o2;
#pragma unroll
    for (int off = 16; off; off >>= 1)
        ss += __shfl_xor_sync(0xffffffffu, ss, off);
    float r = rsqrtf(ss * (1.0f / 64.0f) + RMS_EPS) * qscale;

    o1 *= r; o2 *= r;
    __nv_bfloat16 h1 = __float2bfloat16(o1);
    __nv_bfloat16 h2 = __float2bfloat16(o2);
    size_t obase = ((size_t)(b * H_HEADS + h) * T + t) * DHEAD;
    qhi[obase + lane]      = h1;
    qhi[obase + 32 + lane] = h2;
    qlo[obase + lane]      = __float2bfloat16(o1 - __bfloat162float(h1));
    qlo[obase + 32 + lane] = __float2bfloat16(o2 - __bfloat162float(h2));
}

// ---------------------------------------------------------------------------
// cp.async double-buffered split-precision NT GEMM (unchanged)
// ---------------------------------------------------------------------------
#define KCH2   32
#define ROWB2  80
#define MATB2  (128 * ROWB2)
#define STB2   (4 * MATB2)
#define GEMM_SMEM (2 * STB2)

template <bool FUSE_ROPE>
__global__ __launch_bounds__(256) void gemm_mma(
    const __nv_bfloat16* __restrict__ Ahi, const __nv_bfloat16* __restrict__ Alo,
    const __nv_bfloat16* __restrict__ Bhi, const __nv_bfloat16* __restrict__ Blo,
    float* __restrict__ C,
    const float* __restrict__ cosb, const float* __restrict__ sinb,
    __nv_bfloat16* __restrict__ Ohi, __nv_bfloat16* __restrict__ Olo,
    int M, int N, int K, int T)
{
    extern __shared__ char smem[];
    const uint32_t sb = smem_u32(smem);

    const int tid  = threadIdx.x;
    const int wid  = tid >> 5;
    const int lane = tid & 31;
    const int m0 = blockIdx.y * 128, n0 = blockIdx.x * 128;

    const int wm = (wid & 3) * 32;
    const int wn = (wid >> 2) * 64;

    const int a_row = (lane & 7) + (lane & 8);
    const int a_col = (lane >> 4) * 16;
    const int b_row = (lane & 7) + ((lane >> 4) & 1) * 8;
    const int b_col = ((lane >> 3) & 1) * 16;

    const int grow = tid >> 1;
    const uint32_t s_off = (uint32_t)grow * ROWB2 + (tid & 1) * 32;
    const int gelem = (tid & 1) * 16;

    const __nv_bfloat16* gAh = Ahi + (size_t)(m0 + grow) * K + gelem;
    const __nv_bfloat16* gAl = Alo + (size_t)(m0 + grow) * K + gelem;
    const __nv_bfloat16* gBh = Bhi + (size_t)(n0 + grow) * K + gelem;
    const __nv_bfloat16* gBl = Blo + (size_t)(n0 + grow) * K + gelem;

    float c[2][8][4];
#pragma unroll
    for (int i = 0; i < 2; i++)
#pragma unroll
        for (int j = 0; j < 8; j++)
#pragma unroll
            for (int e = 0; e < 4; e++) c[i][j][e] = 0.f;

    const int nchunk = K / KCH2;

    auto fill = [&](int stage, int ch) {
        const int k0 = ch * KCH2;
        uint32_t s0 = sb + stage * STB2 + s_off;
        const __nv_bfloat16* a0 = gAh + k0;
        const __nv_bfloat16* a1 = gAl + k0;
        const __nv_bfloat16* b0 = gBh + k0;
        const __nv_bfloat16* b1 = gBl + k0;
        CP16(s0,                 a0);      CP16(s0 + 16,                 a0 + 8);
        CP16(s0 + MATB2,         a1);      CP16(s0 + MATB2 + 16,         a1 + 8);
        CP16(s0 + 2 * MATB2,     b0);      CP16(s0 + 2 * MATB2 + 16,     b0 + 8);
        CP16(s0 + 3 * MATB2,     b1);      CP16(s0 + 3 * MATB2 + 16,     b1 + 8);
    };

    fill(0, 0);
    CP_COMMIT();

    for (int ch = 0; ch < nchunk; ch++) {
        const int st = ch & 1;
        if (ch + 1 < nchunk) { fill(st ^ 1, ch + 1); CP_COMMIT(); CP_WAIT1(); }
        else                 { CP_WAIT0(); }
        __syncthreads();

        const uint32_t base = sb + st * STB2;
        const uint32_t sAhi = base, sBhi = base + 2 * MATB2;

#pragma unroll
        for (int ks = 0; ks < 2; ks++) {
            const int kb = ks * 32;
            uint32_t ah[2][4], al[2][4], bh[4][4], bl[4][4];
#pragma unroll
            for (int mi = 0; mi < 2; mi++) {
                uint32_t addr = sAhi + (uint32_t)(wm + mi * 16 + a_row) * ROWB2 + kb + a_col;
                LDSM_X4(ah[mi][0], ah[mi][1], ah[mi][2], ah[mi][3], addr);
                addr += MATB2;
                LDSM_X4(al[mi][0], al[mi][1], al[mi][2], al[mi][3], addr);
            }
#pragma unroll
            for (int nb = 0; nb < 4; nb++) {
                uint32_t addr = sBhi + (uint32_t)(wn + nb * 16 + b_row) * ROWB2 + kb + b_col;
                LDSM_X4(bh[nb][0], bh[nb][1], bh[nb][2], bh[nb][3], addr);
                addr += MATB2;
                LDSM_X4(bl[nb][0], bl[nb][1], bl[nb][2], bl[nb][3], addr);
            }
#pragma unroll
            for (int mi = 0; mi < 2; mi++)
#pragma unroll
                for (int nb = 0; nb < 4; nb++)
#pragma unroll
                    for (int sj = 0; sj < 2; sj++) {
                        float* cc = c[mi][nb * 2 + sj];
                        MMA_BF16(cc[0], cc[1], cc[2], cc[3],
                                 ah[mi][0], ah[mi][1], ah[mi][2], ah[mi][3],
                                 bh[nb][sj * 2], bh[nb][sj * 2 + 1]);
                        MMA_BF16(cc[0], cc[1], cc[2], cc[3],
                                 ah[mi][0], ah[mi][1], ah[mi][2], ah[mi][3],
                                 bl[nb][sj * 2], bl[nb][sj * 2 + 1]);
                        MMA_BF16(cc[0], cc[1], cc[2], cc[3],
                                 al[mi][0], al[mi][1], al[mi][2], al[mi][3],
                                 bh[nb][sj * 2], bh[nb][sj * 2 + 1]);
                    }
        }
        __syncthreads();
    }

    const int g  = lane >> 2;
    const int t2 = (lane & 3) * 2;

    if (!FUSE_ROPE) {
#pragma unroll
        for (int mi = 0; mi < 2; mi++) {
            float* r0 = C + (size_t)(m0 + wm + mi * 16 + g) * N + n0 + wn + t2;
            float* r1 = r0 + 8 * N;
#pragma unroll
            for (int nj = 0; nj < 8; nj++) {
                *(float2*)(r0 + nj * 8) = make_float2(c[mi][nj][0], c[mi][nj][1]);
                *(float2*)(r1 + nj * 8) = make_float2(c[mi][nj][2], c[mi][nj][3]);
            }
        }
    } else {
        const int h = (n0 + wn) >> 6;
#pragma unroll
        for (int mi = 0; mi < 2; mi++) {
#pragma unroll
            for (int half = 0; half < 2; half++) {
                const int m = m0 + wm + mi * 16 + g + half * 8;
                const int b = m / T, t = m % T;
                float o1[4][2], o2[4][2];
                float ss = 0.f;
#pragma unroll
                for (int nj = 0; nj < 4; nj++) {
#pragma unroll
                    for (int e = 0; e < 2; e++) {
                        const int d = nj * 8 + t2 + e;
                        float x1 = c[mi][nj][half * 2 + e];
                        float x2 = c[mi][nj + 4][half * 2 + e];
                        float co = cosb[t * 32 + d];
                        float si = sinb[t * 32 + d];
                        float a = x1 * co + x2 * si;
                        float bb = -x1 * si + x2 * co;
                        o1[nj][e] = a; o2[nj][e] = bb;
                        ss += a * a + bb * bb;
                    }
                }
                ss += __shfl_xor_sync(0xffffffffu, ss, 1);
                ss += __shfl_xor_sync(0xffffffffu, ss, 2);
                float r = rsqrtf(ss * (1.0f / 64.0f) + RMS_EPS);
                const size_t ob = ((size_t)(b * H_HEADS + h) * T + t) * DHEAD + t2;
#pragma unroll
                for (int nj = 0; nj < 4; nj++) {
                    uint32_t hi, lo;
                    split_pack(o1[nj][0] * r, o1[nj][1] * r, hi, lo);
                    *(uint32_t*)(Ohi + ob + nj * 8) = hi;
                    *(uint32_t*)(Olo + ob + nj * 8) = lo;
                    split_pack(o2[nj][0] * r, o2[nj][1] * r, hi, lo);
                    *(uint32_t*)(Ohi + ob + 32 + nj * 8) = hi;
                    *(uint32_t*)(Olo + ob + 32 + nj * 8) = lo;
                }
            }
        }
    }
}

// ---------------------------------------------------------------------------
// Sliding-window attention: 64-q tile, 8 warps = 4 m-warps x 2 key-groups.
// Fixed-max linear softmax -> k-split partials just add (smem reduce at end).
// ---------------------------------------------------------------------------
#define ATT_ROWB 144
#define ATT_MAT  (64 * ATT_ROWB)

__global__ __launch_bounds__(256, 2) void attn_mma(
    const __nv_bfloat16* __restrict__ Qhi, const __nv_bfloat16* __restrict__ Qlo,
    const __nv_bfloat16* __restrict__ KVhi, const __nv_bfloat16* __restrict__ KVlo,
    __nv_bfloat16* __restrict__ Ohi, __nv_bfloat16* __restrict__ Olo,
    const int* __restrict__ wl, int T)
{
    __shared__ char smc[2 * ATT_MAT];   // 18432 B; reused for epilogue reduce
    const uint32_t sKhi = smem_u32(smc);

    const int tid = threadIdx.x, wid = tid >> 5, lane = tid & 31;
    const int mwarp = wid & 3, kgrp = wid >> 2;
    const int qt = blockIdx.x, h = blockIdx.y, b = blockIdx.z;
    const int q0 = qt * 64;
    const int W = *wl;
    const size_t hb = (size_t)(b * H_HEADS + h) * T * DHEAD;

    // staging: 256 threads cover 64 rows x 128B (hi and lo)
    const int lrow = tid >> 2;
    const uint32_t s_off = (uint32_t)lrow * ATT_ROWB + (tid & 3) * 32;
    const int gcol = (tid & 3) * 16;

    const int a_row  = (lane & 7) + (lane & 8);
    const int a_colB = (lane >> 4) * 16;
    const int b_row  = (lane & 7) + ((lane >> 4) & 1) * 8;
    const int b_colB = ((lane >> 3) & 1) * 16;
    const int t_m = lane >> 3, t_r = lane & 7;

    // ---- stage Q -> fragments (each m-warp's 16 rows; both kgrps same) ----
    {
        const uint4* sh = (const uint4*)(Qhi + hb + (size_t)(q0 + lrow) * DHEAD + gcol);
        const uint4* sl = (const uint4*)(Qlo + hb + (size_t)(q0 + lrow) * DHEAD + gcol);
        *(uint4*)(smc + s_off)          = sh[0];
        *(uint4*)(smc + s_off + 16)     = sh[1];
        *(uint4*)(smc + ATT_MAT + s_off)      = sl[0];
        *(uint4*)(smc + ATT_MAT + s_off + 16) = sl[1];
    }
    __syncthreads();
    uint32_t qh[4][4], ql[4][4];
#pragma unroll
    for (int kc = 0; kc < 4; kc++) {
        uint32_t ad = sKhi + (uint32_t)(mwarp * 16 + a_row) * ATT_ROWB + kc * 32 + a_colB;
        LDSM_X4(qh[kc][0], qh[kc][1], qh[kc][2], qh[kc][3], ad);
        LDSM_X4(ql[kc][0], ql[kc][1], ql[kc][2], ql[kc][3], ad + ATT_MAT);
    }

    float o[8][4];
#pragma unroll
    for (int i = 0; i < 8; i++)
#pragma unroll
        for (int e = 0; e < 4; e++) o[i][e] = 0.f;
    float lsum[2] = {0.f, 0.f};

    int lo_t = q0 - W; if (lo_t < 0) lo_t = 0;
    const int kt_lo = lo_t >> 6;

    for (int kt = kt_lo; kt <= qt; kt++) {
        const int k0 = kt * 64;
        __syncthreads();
        {
            const uint4* sh = (const uint4*)(KVhi + hb + (size_t)(k0 + lrow) * DHEAD + gcol);
            const uint4* sl = (const uint4*)(KVlo + hb + (size_t)(k0 + lrow) * DHEAD + gcol);
            *(uint4*)(smc + s_off)          = sh[0];
            *(uint4*)(smc + s_off + 16)     = sh[1];
            *(uint4*)(smc + ATT_MAT + s_off)      = sl[0];
            *(uint4*)(smc + ATT_MAT + s_off + 16) = sl[1];
        }
        __syncthreads();

        const bool fullt = (kt < qt) && (q0 + 63 - k0 <= W);

        // this key-group handles n16 chunks {2*kgrp, 2*kgrp+1}
#pragma unroll
        for (int nc = 0; nc < 2; nc++) {
            const int n16 = kgrp * 2 + nc;

            float s[2][4];
#pragma unroll
            for (int sj = 0; sj < 2; sj++)
#pragma unroll
                for (int e = 0; e < 4; e++) s[sj][e] = 0.f;

#pragma unroll
            for (int kc = 0; kc < 4; kc++) {
                uint32_t bh[4], bl[4];
                uint32_t ad = sKhi + (uint32_t)(n16 * 16 + b_row) * ATT_ROWB + kc * 32 + b_colB;
                LDSM_X4(bh[0], bh[1], bh[2], bh[3], ad);
                LDSM_X4(bl[0], bl[1], bl[2], bl[3], ad + ATT_MAT);
#pragma unroll
                for (int sj = 0; sj < 2; sj++) {
                    float* cc = s[sj];
                    MMA_BF16(cc[0], cc[1], cc[2], cc[3],
                             qh[kc][0], qh[kc][1], qh[kc][2], qh[kc][3],
                             bh[sj * 2], bh[sj * 2 + 1]);
                    MMA_BF16(cc[0], cc[1], cc[2], cc[3],
                             qh[kc][0], qh[kc][1], qh[kc][2], qh[kc][3],
                             bl[sj * 2], bl[sj * 2 + 1]);
                    MMA_BF16(cc[0], cc[1], cc[2], cc[3],
                             ql[kc][0], ql[kc][1], ql[kc][2], ql[kc][3],
                             bh[sj * 2], bh[sj * 2 + 1]);
                }
            }

            if (!fullt) {
                const int qr = q0 + mwarp * 16 + (lane >> 2);
#pragma unroll
                for (int sj = 0; sj < 2; sj++) {
                    const int kb = k0 + (n16 * 2 + sj) * 8 + (lane & 3) * 2;
#pragma unroll
                    for (int e = 0; e < 4; e++) {
                        int qq = qr + ((e >= 2) ? 8 : 0);
                        int kk = kb + (e & 1);
                        if (kk > qq || qq - kk > W) s[sj][e] = -1e30f;
                    }
                }
            }

            uint32_t ph[4], pl[4];
#pragma unroll
            for (int sj = 0; sj < 2; sj++)
#pragma unroll
                for (int e = 0; e < 4; e++) {
                    float p = exp2f(s[sj][e] - FIXMAX);
                    s[sj][e] = p;
                    lsum[e >> 1] += p;
                }
            split_pack(s[0][0], s[0][1], ph[0], pl[0]);
            split_pack(s[0][2], s[0][3], ph[1], pl[1]);
            split_pack(s[1][0], s[1][1], ph[2], pl[2]);
            split_pack(s[1][2], s[1][3], ph[3], pl[3]);

#pragma unroll
            for (int dg = 0; dg < 4; dg++) {
                uint32_t vh[4], vl[4];
                uint32_t ad = sKhi + (uint32_t)(n16 * 16 + t_r + (t_m & 1) * 8) * ATT_ROWB
                            + dg * 32 + (t_m >> 1) * 16;
                LDSM_X4_T(vh[0], vh[1], vh[2], vh[3], ad);
                LDSM_X4_T(vl[0], vl[1], vl[2], vl[3], ad + ATT_MAT);
#pragma unroll
                for (int sj = 0; sj < 2; sj++) {
                    float* cc = o[dg * 2 + sj];
                    MMA_BF16(cc[0], cc[1], cc[2], cc[3],
                             ph[0], ph[1], ph[2], ph[3],
                             vh[sj * 2], vh[sj * 2 + 1]);
                    MMA_BF16(cc[0], cc[1], cc[2], cc[3],
                             pl[0], pl[1], pl[2], pl[3],
                             vh[sj * 2], vh[sj * 2 + 1]);
                    MMA_BF16(cc[0], cc[1], cc[2], cc[3],
                             ph[0], ph[1], ph[2], ph[3],
                             vl[sj * 2], vl[sj * 2 + 1]);
                }
            }
        }
    }

    // ---- epilogue: cross-group reduce via smem (partials simply add) ----
    __syncthreads();
    float* red = (float*)smc;
    if (kgrp == 1) {
        float* dst = red + (tid - 128) * 34;
#pragma unroll
        for (int i = 0; i < 8; i++)
#pragma unroll
            for (int e = 0; e < 4; e++) dst[i * 4 + e] = o[i][e];
        dst[32] = lsum[0];
        dst[33] = lsum[1];
    }
    __syncthreads();
    if (kgrp == 0) {
        const float* src = red + tid * 34;
#pragma unroll
        for (int i = 0; i < 8; i++)
#pragma unroll
            for (int e = 0; e < 4; e++) o[i][e] += src[i * 4 + e];
        lsum[0] += src[32];
        lsum[1] += src[33];

        lsum[0] += __shfl_xor_sync(0xffffffffu, lsum[0], 1);
        lsum[0] += __shfl_xor_sync(0xffffffffu, lsum[0], 2);
        lsum[1] += __shfl_xor_sync(0xffffffffu, lsum[1], 1);
        lsum[1] += __shfl_xor_sync(0xffffffffu, lsum[1], 2);
        const float inv0 = 1.f / lsum[0];
        const float inv1 = 1.f / lsum[1];
        const int g = lane >> 2, t2 = (lane & 3) * 2;
        const size_t r0 = (size_t)(b * T + q0 + mwarp * 16 + g) * 1024 + h * 64 + t2;
        const size_t r1 = r0 + (size_t)8 * 1024;
#pragma unroll
        for (int nj = 0; nj < 8; nj++) {
            uint32_t hi, lo;
            split_pack(o[nj][0] * inv0, o[nj][1] * inv0, hi, lo);
            *(uint32_t*)(Ohi + r0 + nj * 8) = hi;
            *(uint32_t*)(Olo + r0 + nj * 8) = lo;
            split_pack(o[nj][2] * inv1, o[nj][3] * inv1, hi, lo);
            *(uint32_t*)(Ohi + r1 + nj * 8) = hi;
            *(uint32_t*)(Olo + r1 + nj * 8) = lo;
        }
    }
}

// ---------------------------------------------------------------------------
extern "C" void kernel_launch(void* const* d_in, const int* in_sizes, int n_in,
                              void* d_out, int out_size)
{
    const float* x      = (const float*)d_in[0];
    const float* cosb   = (const float*)d_in[1];
    const float* sinb   = (const float*)d_in[2];
    const float* kv_w   = (const float*)d_in[3];
    const float* proj_w = (const float*)d_in[4];
    const int* wl       = (n_in >= 6) ? (const int*)d_in[5] : nullptr;

    const int T = in_sizes[1] / 32;
    const int C = 1024;
    const int B = in_sizes[0] / (T * C);
    const int M = B * T;
    const int total_heads = M * H_HEADS;

    __nv_bfloat16 *ahi, *alo, *bhi, *blo, *qhi, *qlo, *kvhi, *kvlo;
    cudaGetSymbolAddress((void**)&ahi,  g_ahi);
    cudaGetSymbolAddress((void**)&alo,  g_alo);
    cudaGetSymbolAddress((void**)&bhi,  g_bhi);
    cudaGetSymbolAddress((void**)&blo,  g_blo);
    cudaGetSymbolAddress((void**)&qhi,  g_qhi);
    cudaGetSymbolAddress((void**)&qlo,  g_qlo);
    cudaGetSymbolAddress((void**)&kvhi, g_kvhi);
    cudaGetSymbolAddress((void**)&kvlo, g_kvlo);

    cudaFuncSetAttribute(gemm_mma<true>,  cudaFuncAttributeMaxDynamicSharedMemorySize, GEMM_SMEM);
    cudaFuncSetAttribute(gemm_mma<false>, cudaFuncAttributeMaxDynamicSharedMemorySize, GEMM_SMEM);

    {
        int blocks = (total_heads + 7) / 8;
        prep_q<<<blocks, 256>>>(x, cosb, sinb, ahi, alo, qhi, qlo,
                                0.125f * LOG2E, T, total_heads);
    }
    split_bf16<<<(C * C / 4 + 255) / 256, 256>>>(kv_w, bhi, blo, C * C / 4);
    {
        dim3 grid(C / 128, M / 128);
        gemm_mma<true><<<grid, 256, GEMM_SMEM>>>(ahi, alo, bhi, blo, nullptr,
                                                 cosb, sinb, kvhi, kvlo, M, C, C, T);
    }
    {
        dim3 grid(T / 64, H_HEADS, B);
        attn_mma<<<grid, 256>>>(qhi, qlo, kvhi, kvlo, ahi, alo, wl, T);
    }
    split_bf16<<<(C * C / 4 + 255) / 256, 256>>>(proj_w, bhi, blo, C * C / 4);
    {
        dim3 grid(C / 128, M / 128);
        gemm_mma<false><<<grid, 256, GEMM_SMEM>>>(ahi, alo, bhi, blo, (float*)d_out,
                                                  nullptr, nullptr, nullptr, nullptr, M, C, C, T);
    }
}

// round 11
// speedup vs baseline: 1.0901x; 1.0206x over previous
#include <cuda_runtime.h>
#include <cuda_bf16.h>
#include <cstdint>

#define H_HEADS 16
#define DHEAD   64
#define RMS_EPS 1.1920928955078125e-07f
#define MAXTOK  4096
#define LOG2E   1.4426950408889634f
#define FIXMAX  12.0f

// ---------------- scratch ----------------
__device__ __nv_bfloat16 g_ahi [MAXTOK * 1024];
__device__ __nv_bfloat16 g_alo [MAXTOK * 1024];
__device__ __nv_bfloat16 g_bhi [1024 * 1024];
__device__ __nv_bfloat16 g_blo [1024 * 1024];
__device__ __nv_bfloat16 g_qhi [MAXTOK * 1024];
__device__ __nv_bfloat16 g_qlo [MAXTOK * 1024];
__device__ __nv_bfloat16 g_kvhi[MAXTOK * 1024];
__device__ __nv_bfloat16 g_kvlo[MAXTOK * 1024];

// ---------------- helpers ----------------
__device__ __forceinline__ uint32_t smem_u32(const void* p) {
    uint32_t a;
    asm("{ .reg .u64 t; cvta.to.shared.u64 t, %1; cvt.u32.u64 %0, t; }" : "=r"(a) : "l"(p));
    return a;
}

#define LDSM_X4(r0, r1, r2, r3, addr) \
    asm volatile("ldmatrix.sync.aligned.m8n8.x4.shared.b16 {%0,%1,%2,%3}, [%4];" \
                 : "=r"(r0), "=r"(r1), "=r"(r2), "=r"(r3) : "r"(addr))

#define LDSM_X4_T(r0, r1, r2, r3, addr) \
    asm volatile("ldmatrix.sync.aligned.m8n8.x4.trans.shared.b16 {%0,%1,%2,%3}, [%4];" \
                 : "=r"(r0), "=r"(r1), "=r"(r2), "=r"(r3) : "r"(addr))

#define MMA_BF16(c0, c1, c2, c3, a0, a1, a2, a3, b0, b1) \
    asm volatile("mma.sync.aligned.m16n8k16.row.col.f32.bf16.bf16.f32 " \
                 "{%0,%1,%2,%3}, {%4,%5,%6,%7}, {%8,%9}, {%0,%1,%2,%3};" \
                 : "+f"(c0), "+f"(c1), "+f"(c2), "+f"(c3) \
                 : "r"(a0), "r"(a1), "r"(a2), "r"(a3), "r"(b0), "r"(b1))

#define CP16(saddr, gptr) \
    asm volatile("cp.async.cg.shared.global [%0], [%1], 16;" :: "r"(saddr), "l"(gptr))
#define CPA16(saddr, gptr) \
    asm volatile("cp.async.ca.shared.global [%0], [%1], 16;" :: "r"(saddr), "l"(gptr))
#define CP_COMMIT() asm volatile("cp.async.commit_group;" ::: "memory")
#define CP_WAIT1()  asm volatile("cp.async.wait_group 1;" ::: "memory")
#define CP_WAIT0()  asm volatile("cp.async.wait_group 0;" ::: "memory")

__device__ __forceinline__ uint32_t pack_bf2(__nv_bfloat16 a, __nv_bfloat16 b) {
    __nv_bfloat162 t(a, b);
    return *(uint32_t*)&t;
}
__device__ __forceinline__ void split_pack(float x, float y, uint32_t& hi, uint32_t& lo) {
    __nv_bfloat16 hx = __float2bfloat16(x), hy = __float2bfloat16(y);
    __nv_bfloat16 lx = __float2bfloat16(x - __bfloat162float(hx));
    __nv_bfloat16 ly = __float2bfloat16(y - __bfloat162float(hy));
    hi = pack_bf2(hx, hy);
    lo = pack_bf2(lx, ly);
}

// ---------------------------------------------------------------------------
__global__ __launch_bounds__(256) void split_bf16(
    const float* __restrict__ in, __nv_bfloat16* __restrict__ hi,
    __nv_bfloat16* __restrict__ lo, int n4)
{
    int i = blockIdx.x * blockDim.x + threadIdx.x;
    if (i >= n4) return;
    float4 v = ((const float4*)in)[i];
    uint32_t h0, l0, h1, l1;
    split_pack(v.x, v.y, h0, l0);
    split_pack(v.z, v.w, h1, l1);
    ((uint32_t*)hi)[2 * i]     = h0;
    ((uint32_t*)hi)[2 * i + 1] = h1;
    ((uint32_t*)lo)[2 * i]     = l0;
    ((uint32_t*)lo)[2 * i + 1] = l1;
}

// ---------------------------------------------------------------------------
__global__ __launch_bounds__(256) void prep_q(
    const float* __restrict__ x, const float* __restrict__ cosb,
    const float* __restrict__ sinb,
    __nv_bfloat16* __restrict__ ahi, __nv_bfloat16* __restrict__ alo,
    __nv_bfloat16* __restrict__ qhi, __nv_bfloat16* __restrict__ qlo,
    float qscale, int T, int total_heads)
{
    int w = blockIdx.x * 8 + (threadIdx.x >> 5);
    if (w >= total_heads) return;
    int lane = threadIdx.x & 31;
    int h = w % H_HEADS;
    int t = (w / H_HEADS) % T;
    int b = w / (H_HEADS * T);

    size_t ibase = (size_t)w * DHEAD;
    float x1 = x[ibase + lane];
    float x2 = x[ibase + 32 + lane];

    {
        __nv_bfloat16 h1 = __float2bfloat16(x1);
        __nv_bfloat16 h2 = __float2bfloat16(x2);
        ahi[ibase + lane]      = h1;
        ahi[ibase + 32 + lane] = h2;
        alo[ibase + lane]      = __float2bfloat16(x1 - __bfloat162float(h1));
        alo[ibase + 32 + lane] = __float2bfloat16(x2 - __bfloat162float(h2));
    }

    float c  = cosb[t * 32 + lane];
    float s  = sinb[t * 32 + lane];
    float o1 = x1 * c + x2 * s;
    float o2 = -x1 * s + x2 * c;

    float ss = o1 * o1 + o2 * o2;
#pragma unroll
    for (int off = 16; off; off >>= 1)
        ss += __shfl_xor_sync(0xffffffffu, ss, off);
    float r = rsqrtf(ss * (1.0f / 64.0f) + RMS_EPS) * qscale;

    o1 *= r; o2 *= r;
    __nv_bfloat16 h1 = __float2bfloat16(o1);
    __nv_bfloat16 h2 = __float2bfloat16(o2);
    size_t obase = ((size_t)(b * H_HEADS + h) * T + t) * DHEAD;
    qhi[obase + lane]      = h1;
    qhi[obase + 32 + lane] = h2;
    qlo[obase + lane]      = __float2bfloat16(o1 - __bfloat162float(h1));
    qlo[obase + 32 + lane] = __float2bfloat16(o2 - __bfloat162float(h2));
}

// ---------------------------------------------------------------------------
// cp.async double-buffered split-precision NT GEMM.
// Inner loop reordered term-outer: 16 independent accumulators between
// dependent reuses of the same accumulator.
// ---------------------------------------------------------------------------
#define KCH2   32
#define ROWB2  80
#define MATB2  (128 * ROWB2)
#define STB2   (4 * MATB2)
#define GEMM_SMEM (2 * STB2)

template <bool FUSE_ROPE>
__global__ __launch_bounds__(256) void gemm_mma(
    const __nv_bfloat16* __restrict__ Ahi, const __nv_bfloat16* __restrict__ Alo,
    const __nv_bfloat16* __restrict__ Bhi, const __nv_bfloat16* __restrict__ Blo,
    float* __restrict__ C,
    const float* __restrict__ cosb, const float* __restrict__ sinb,
    __nv_bfloat16* __restrict__ Ohi, __nv_bfloat16* __restrict__ Olo,
    int M, int N, int K, int T)
{
    extern __shared__ char smem[];
    const uint32_t sb = smem_u32(smem);

    const int tid  = threadIdx.x;
    const int wid  = tid >> 5;
    const int lane = tid & 31;
    const int m0 = blockIdx.y * 128, n0 = blockIdx.x * 128;

    const int wm = (wid & 3) * 32;
    const int wn = (wid >> 2) * 64;

    const int a_row = (lane & 7) + (lane & 8);
    const int a_col = (lane >> 4) * 16;
    const int b_row = (lane & 7) + ((lane >> 4) & 1) * 8;
    const int b_col = ((lane >> 3) & 1) * 16;

    const int grow = tid >> 1;
    const uint32_t s_off = (uint32_t)grow * ROWB2 + (tid & 1) * 32;
    const int gelem = (tid & 1) * 16;

    const __nv_bfloat16* gAh = Ahi + (size_t)(m0 + grow) * K + gelem;
    const __nv_bfloat16* gAl = Alo + (size_t)(m0 + grow) * K + gelem;
    const __nv_bfloat16* gBh = Bhi + (size_t)(n0 + grow) * K + gelem;
    const __nv_bfloat16* gBl = Blo + (size_t)(n0 + grow) * K + gelem;

    float c[2][8][4];
#pragma unroll
    for (int i = 0; i < 2; i++)
#pragma unroll
        for (int j = 0; j < 8; j++)
#pragma unroll
            for (int e = 0; e < 4; e++) c[i][j][e] = 0.f;

    const int nchunk = K / KCH2;

    auto fill = [&](int stage, int ch) {
        const int k0 = ch * KCH2;
        uint32_t s0 = sb + stage * STB2 + s_off;
        const __nv_bfloat16* a0 = gAh + k0;
        const __nv_bfloat16* a1 = gAl + k0;
        const __nv_bfloat16* b0 = gBh + k0;
        const __nv_bfloat16* b1 = gBl + k0;
        CP16(s0,                 a0);      CP16(s0 + 16,                 a0 + 8);
        CP16(s0 + MATB2,         a1);      CP16(s0 + MATB2 + 16,         a1 + 8);
        CP16(s0 + 2 * MATB2,     b0);      CP16(s0 + 2 * MATB2 + 16,     b0 + 8);
        CP16(s0 + 3 * MATB2,     b1);      CP16(s0 + 3 * MATB2 + 16,     b1 + 8);
    };

    fill(0, 0);
    CP_COMMIT();

    for (int ch = 0; ch < nchunk; ch++) {
        const int st = ch & 1;
        if (ch + 1 < nchunk) { fill(st ^ 1, ch + 1); CP_COMMIT(); CP_WAIT1(); }
        else                 { CP_WAIT0(); }
        __syncthreads();

        const uint32_t base = sb + st * STB2;
        const uint32_t sAhi = base, sBhi = base + 2 * MATB2;

#pragma unroll
        for (int ks = 0; ks < 2; ks++) {
            const int kb = ks * 32;
            uint32_t ah[2][4], al[2][4], bh[4][4], bl[4][4];
#pragma unroll
            for (int mi = 0; mi < 2; mi++) {
                uint32_t addr = sAhi + (uint32_t)(wm + mi * 16 + a_row) * ROWB2 + kb + a_col;
                LDSM_X4(ah[mi][0], ah[mi][1], ah[mi][2], ah[mi][3], addr);
                addr += MATB2;
                LDSM_X4(al[mi][0], al[mi][1], al[mi][2], al[mi][3], addr);
            }
#pragma unroll
            for (int nb = 0; nb < 4; nb++) {
                uint32_t addr = sBhi + (uint32_t)(wn + nb * 16 + b_row) * ROWB2 + kb + b_col;
                LDSM_X4(bh[nb][0], bh[nb][1], bh[nb][2], bh[nb][3], addr);
                addr += MATB2;
                LDSM_X4(bl[nb][0], bl[nb][1], bl[nb][2], bl[nb][3], addr);
            }
            // term-outer passes: 16 independent accumulators per pass
#pragma unroll
            for (int mi = 0; mi < 2; mi++)
#pragma unroll
                for (int nb = 0; nb < 4; nb++)
#pragma unroll
                    for (int sj = 0; sj < 2; sj++) {
                        float* cc = c[mi][nb * 2 + sj];
                        MMA_BF16(cc[0], cc[1], cc[2], cc[3],
                                 ah[mi][0], ah[mi][1], ah[mi][2], ah[mi][3],
                                 bh[nb][sj * 2], bh[nb][sj * 2 + 1]);
                    }
#pragma unroll
            for (int mi = 0; mi < 2; mi++)
#pragma unroll
                for (int nb = 0; nb < 4; nb++)
#pragma unroll
                    for (int sj = 0; sj < 2; sj++) {
                        float* cc = c[mi][nb * 2 + sj];
                        MMA_BF16(cc[0], cc[1], cc[2], cc[3],
                                 ah[mi][0], ah[mi][1], ah[mi][2], ah[mi][3],
                                 bl[nb][sj * 2], bl[nb][sj * 2 + 1]);
                    }
#pragma unroll
            for (int mi = 0; mi < 2; mi++)
#pragma unroll
                for (int nb = 0; nb < 4; nb++)
#pragma unroll
                    for (int sj = 0; sj < 2; sj++) {
                        float* cc = c[mi][nb * 2 + sj];
                        MMA_BF16(cc[0], cc[1], cc[2], cc[3],
                                 al[mi][0], al[mi][1], al[mi][2], al[mi][3],
                                 bh[nb][sj * 2], bh[nb][sj * 2 + 1]);
                    }
        }
        __syncthreads();
    }

    const int g  = lane >> 2;
    const int t2 = (lane & 3) * 2;

    if (!FUSE_ROPE) {
#pragma unroll
        for (int mi = 0; mi < 2; mi++) {
            float* r0 = C + (size_t)(m0 + wm + mi * 16 + g) * N + n0 + wn + t2;
            float* r1 = r0 + 8 * N;
#pragma unroll
            for (int nj = 0; nj < 8; nj++) {
                *(float2*)(r0 + nj * 8) = make_float2(c[mi][nj][0], c[mi][nj][1]);
                *(float2*)(r1 + nj * 8) = make_float2(c[mi][nj][2], c[mi][nj][3]);
            }
        }
    } else {
        const int h = (n0 + wn) >> 6;
#pragma unroll
        for (int mi = 0; mi < 2; mi++) {
#pragma unroll
            for (int half = 0; half < 2; half++) {
                const int m = m0 + wm + mi * 16 + g + half * 8;
                const int b = m / T, t = m % T;
                float o1[4][2], o2[4][2];
                float ss = 0.f;
#pragma unroll
                for (int nj = 0; nj < 4; nj++) {
#pragma unroll
                    for (int e = 0; e < 2; e++) {
                        const int d = nj * 8 + t2 + e;
                        float x1 = c[mi][nj][half * 2 + e];
                        float x2 = c[mi][nj + 4][half * 2 + e];
                        float co = cosb[t * 32 + d];
                        float si = sinb[t * 32 + d];
                        float a = x1 * co + x2 * si;
                        float bb = -x1 * si + x2 * co;
                        o1[nj][e] = a; o2[nj][e] = bb;
                        ss += a * a + bb * bb;
                    }
                }
                ss += __shfl_xor_sync(0xffffffffu, ss, 1);
                ss += __shfl_xor_sync(0xffffffffu, ss, 2);
                float r = rsqrtf(ss * (1.0f / 64.0f) + RMS_EPS);
                const size_t ob = ((size_t)(b * H_HEADS + h) * T + t) * DHEAD + t2;
#pragma unroll
                for (int nj = 0; nj < 4; nj++) {
                    uint32_t hi, lo;
                    split_pack(o1[nj][0] * r, o1[nj][1] * r, hi, lo);
                    *(uint32_t*)(Ohi + ob + nj * 8) = hi;
                    *(uint32_t*)(Olo + ob + nj * 8) = lo;
                    split_pack(o2[nj][0] * r, o2[nj][1] * r, hi, lo);
                    *(uint32_t*)(Ohi + ob + 32 + nj * 8) = hi;
                    *(uint32_t*)(Olo + ob + 32 + nj * 8) = lo;
                }
            }
        }
    }
}

// ---------------------------------------------------------------------------
// Sliding-window attention: 64-q tile, 8 warps = 4 m-warps x 2 key-groups,
// cp.async.ca double-buffered KV (L1-allocating), fixed-max linear softmax,
// dependency-spread MMA ordering.
// ---------------------------------------------------------------------------
#define ATT_ROWB 144
#define ATT_MAT  (64 * ATT_ROWB)
#define ATT_STG  (2 * ATT_MAT)

__global__ __launch_bounds__(256, 2) void attn_mma(
    const __nv_bfloat16* __restrict__ Qhi, const __nv_bfloat16* __restrict__ Qlo,
    const __nv_bfloat16* __restrict__ KVhi, const __nv_bfloat16* __restrict__ KVlo,
    __nv_bfloat16* __restrict__ Ohi, __nv_bfloat16* __restrict__ Olo,
    const int* __restrict__ wl, int T)
{
    __shared__ char smc[2 * ATT_STG];   // 36864 B, 2 stages
    const uint32_t sbase = smem_u32(smc);

    const int tid = threadIdx.x, wid = tid >> 5, lane = tid & 31;
    const int mwarp = wid & 3, kgrp = wid >> 2;
    const int qt = blockIdx.x, h = blockIdx.y, b = blockIdx.z;
    const int q0 = qt * 64;
    const int W = *wl;
    const size_t hb = (size_t)(b * H_HEADS + h) * T * DHEAD;

    const int lrow = tid >> 2;
    const uint32_t s_off = (uint32_t)lrow * ATT_ROWB + (tid & 3) * 32;
    const int gcol = (tid & 3) * 16;

    const int a_row  = (lane & 7) + (lane & 8);
    const int a_colB = (lane >> 4) * 16;
    const int b_row  = (lane & 7) + ((lane >> 4) & 1) * 8;
    const int b_colB = ((lane >> 3) & 1) * 16;
    const int t_m = lane >> 3, t_r = lane & 7;

    auto fill_kv = [&](int st, int k0) {
        uint32_t s0 = sbase + st * ATT_STG + s_off;
        const __nv_bfloat16* gh = KVhi + hb + (size_t)(k0 + lrow) * DHEAD + gcol;
        const __nv_bfloat16* gl = KVlo + hb + (size_t)(k0 + lrow) * DHEAD + gcol;
        CPA16(s0,      gh);  CPA16(s0 + 16,      gh + 8);
        CPA16(s0 + ATT_MAT, gl);  CPA16(s0 + ATT_MAT + 16, gl + 8);
    };

    // ---- stage Q through stage 0 -> fragments ----
    {
        uint32_t s0 = sbase + s_off;
        const __nv_bfloat16* gh = Qhi + hb + (size_t)(q0 + lrow) * DHEAD + gcol;
        const __nv_bfloat16* gl = Qlo + hb + (size_t)(q0 + lrow) * DHEAD + gcol;
        CPA16(s0,      gh);  CPA16(s0 + 16,      gh + 8);
        CPA16(s0 + ATT_MAT, gl);  CPA16(s0 + ATT_MAT + 16, gl + 8);
        CP_COMMIT();
        CP_WAIT0();
    }
    __syncthreads();
    uint32_t qh[4][4], ql[4][4];
#pragma unroll
    for (int kc = 0; kc < 4; kc++) {
        uint32_t ad = sbase + (uint32_t)(mwarp * 16 + a_row) * ATT_ROWB + kc * 32 + a_colB;
        LDSM_X4(qh[kc][0], qh[kc][1], qh[kc][2], qh[kc][3], ad);
        LDSM_X4(ql[kc][0], ql[kc][1], ql[kc][2], ql[kc][3], ad + ATT_MAT);
    }
    __syncthreads();

    float o[8][4];
#pragma unroll
    for (int i = 0; i < 8; i++)
#pragma unroll
        for (int e = 0; e < 4; e++) o[i][e] = 0.f;
    float lsum[2] = {0.f, 0.f};

    int lo_t = q0 - W; if (lo_t < 0) lo_t = 0;
    const int kt_lo = lo_t >> 6;

    fill_kv(0, kt_lo * 64);
    CP_COMMIT();

    for (int kt = kt_lo; kt <= qt; kt++) {
        const int k0 = kt * 64;
        const int st = (kt - kt_lo) & 1;
        if (kt < qt) { fill_kv(st ^ 1, k0 + 64); CP_COMMIT(); CP_WAIT1(); }
        else         { CP_WAIT0(); }
        __syncthreads();

        const uint32_t sKhi = sbase + st * ATT_STG;
        const bool fullt = (kt < qt) && (q0 + 63 - k0 <= W);

#pragma unroll
        for (int nc = 0; nc < 2; nc++) {
            const int n16 = kgrp * 2 + nc;

            float s[2][4];
#pragma unroll
            for (int sj = 0; sj < 2; sj++)
#pragma unroll
                for (int e = 0; e < 4; e++) s[sj][e] = 0.f;

#pragma unroll
            for (int kc = 0; kc < 4; kc++) {
                uint32_t bh[4], bl[4];
                uint32_t ad = sKhi + (uint32_t)(n16 * 16 + b_row) * ATT_ROWB + kc * 32 + b_colB;
                LDSM_X4(bh[0], bh[1], bh[2], bh[3], ad);
                LDSM_X4(bl[0], bl[1], bl[2], bl[3], ad + ATT_MAT);
                // term-major: alternate sj between dependent reuses
                MMA_BF16(s[0][0], s[0][1], s[0][2], s[0][3],
                         qh[kc][0], qh[kc][1], qh[kc][2], qh[kc][3], bh[0], bh[1]);
                MMA_BF16(s[1][0], s[1][1], s[1][2], s[1][3],
                         qh[kc][0], qh[kc][1], qh[kc][2], qh[kc][3], bh[2], bh[3]);
                MMA_BF16(s[0][0], s[0][1], s[0][2], s[0][3],
                         qh[kc][0], qh[kc][1], qh[kc][2], qh[kc][3], bl[0], bl[1]);
                MMA_BF16(s[1][0], s[1][1], s[1][2], s[1][3],
                         qh[kc][0], qh[kc][1], qh[kc][2], qh[kc][3], bl[2], bl[3]);
                MMA_BF16(s[0][0], s[0][1], s[0][2], s[0][3],
                         ql[kc][0], ql[kc][1], ql[kc][2], ql[kc][3], bh[0], bh[1]);
                MMA_BF16(s[1][0], s[1][1], s[1][2], s[1][3],
                         ql[kc][0], ql[kc][1], ql[kc][2], ql[kc][3], bh[2], bh[3]);
            }

            if (!fullt) {
                const int qr = q0 + mwarp * 16 + (lane >> 2);
#pragma unroll
                for (int sj = 0; sj < 2; sj++) {
                    const int kb = k0 + (n16 * 2 + sj) * 8 + (lane & 3) * 2;
#pragma unroll
                    for (int e = 0; e < 4; e++) {
                        int qq = qr + ((e >= 2) ? 8 : 0);
                        int kk = kb + (e & 1);
                        if (kk > qq || qq - kk > W) s[sj][e] = -1e30f;
                    }
                }
            }

            uint32_t ph[4], pl[4];
#pragma unroll
            for (int sj = 0; sj < 2; sj++)
#pragma unroll
                for (int e = 0; e < 4; e++) {
                    float p = exp2f(s[sj][e] - FIXMAX);
                    s[sj][e] = p;
                    lsum[e >> 1] += p;
                }
            split_pack(s[0][0], s[0][1], ph[0], pl[0]);
            split_pack(s[0][2], s[0][3], ph[1], pl[1]);
            split_pack(s[1][0], s[1][1], ph[2], pl[2]);
            split_pack(s[1][2], s[1][3], ph[3], pl[3]);

#pragma unroll
            for (int dg = 0; dg < 4; dg++) {
                uint32_t vh[4], vl[4];
                uint32_t ad = sKhi + (uint32_t)(n16 * 16 + t_r + (t_m & 1) * 8) * ATT_ROWB
                            + dg * 32 + (t_m >> 1) * 16;
                LDSM_X4_T(vh[0], vh[1], vh[2], vh[3], ad);
                LDSM_X4_T(vl[0], vl[1], vl[2], vl[3], ad + ATT_MAT);
                float* c0 = o[dg * 2];
                float* c1 = o[dg * 2 + 1];
                MMA_BF16(c0[0], c0[1], c0[2], c0[3], ph[0], ph[1], ph[2], ph[3], vh[0], vh[1]);
                MMA_BF16(c1[0], c1[1], c1[2], c1[3], ph[0], ph[1], ph[2], ph[3], vh[2], vh[3]);
                MMA_BF16(c0[0], c0[1], c0[2], c0[3], pl[0], pl[1], pl[2], pl[3], vh[0], vh[1]);
                MMA_BF16(c1[0], c1[1], c1[2], c1[3], pl[0], pl[1], pl[2], pl[3], vh[2], vh[3]);
                MMA_BF16(c0[0], c0[1], c0[2], c0[3], ph[0], ph[1], ph[2], ph[3], vl[0], vl[1]);
                MMA_BF16(c1[0], c1[1], c1[2], c1[3], ph[0], ph[1], ph[2], ph[3], vl[2], vl[3]);
            }
        }
        __syncthreads();
    }

    // ---- epilogue: cross-group reduce via smem (linear partials add) ----
    float* red = (float*)smc;
    if (kgrp == 1) {
        float* dst = red + (tid - 128) * 34;
#pragma unroll
        for (int i = 0; i < 8; i++)
#pragma unroll
            for (int e = 0; e < 4; e++) dst[i * 4 + e] = o[i][e];
        dst[32] = lsum[0];
        dst[33] = lsum[1];
    }
    __syncthreads();
    if (kgrp == 0) {
        const float* src = red + tid * 34;
#pragma unroll
        for (int i = 0; i < 8; i++)
#pragma unroll
            for (int e = 0; e < 4; e++) o[i][e] += src[i * 4 + e];
        lsum[0] += src[32];
        lsum[1] += src[33];

        lsum[0] += __shfl_xor_sync(0xffffffffu, lsum[0], 1);
        lsum[0] += __shfl_xor_sync(0xffffffffu, lsum[0], 2);
        lsum[1] += __shfl_xor_sync(0xffffffffu, lsum[1], 1);
        lsum[1] += __shfl_xor_sync(0xffffffffu, lsum[1], 2);
        const float inv0 = 1.f / lsum[0];
        const float inv1 = 1.f / lsum[1];
        const int g = lane >> 2, t2 = (lane & 3) * 2;
        const size_t r0 = (size_t)(b * T + q0 + mwarp * 16 + g) * 1024 + h * 64 + t2;
        const size_t r1 = r0 + (size_t)8 * 1024;
#pragma unroll
        for (int nj = 0; nj < 8; nj++) {
            uint32_t hi, lo;
            split_pack(o[nj][0] * inv0, o[nj][1] * inv0, hi, lo);
            *(uint32_t*)(Ohi + r0 + nj * 8) = hi;
            *(uint32_t*)(Olo + r0 + nj * 8) = lo;
            split_pack(o[nj][2] * inv1, o[nj][3] * inv1, hi, lo);
            *(uint32_t*)(Ohi + r1 + nj * 8) = hi;
            *(uint32_t*)(Olo + r1 + nj * 8) = lo;
        }
    }
}

// ---------------------------------------------------------------------------
extern "C" void kernel_launch(void* const* d_in, const int* in_sizes, int n_in,
                              void* d_out, int out_size)
{
    const float* x      = (const float*)d_in[0];
    const float* cosb   = (const float*)d_in[1];
    const float* sinb   = (const float*)d_in[2];
    const float* kv_w   = (const float*)d_in[3];
    const float* proj_w = (const float*)d_in[4];
    const int* wl       = (n_in >= 6) ? (const int*)d_in[5] : nullptr;

    const int T = in_sizes[1] / 32;
    const int C = 1024;
    const int B = in_sizes[0] / (T * C);
    const int M = B * T;
    const int total_heads = M * H_HEADS;

    __nv_bfloat16 *ahi, *alo, *bhi, *blo, *qhi, *qlo, *kvhi, *kvlo;
    cudaGetSymbolAddress((void**)&ahi,  g_ahi);
    cudaGetSymbolAddress((void**)&alo,  g_alo);
    cudaGetSymbolAddress((void**)&bhi,  g_bhi);
    cudaGetSymbolAddress((void**)&blo,  g_blo);
    cudaGetSymbolAddress((void**)&qhi,  g_qhi);
    cudaGetSymbolAddress((void**)&qlo,  g_qlo);
    cudaGetSymbolAddress((void**)&kvhi, g_kvhi);
    cudaGetSymbolAddress((void**)&kvlo, g_kvlo);

    cudaFuncSetAttribute(gemm_mma<true>,  cudaFuncAttributeMaxDynamicSharedMemorySize, GEMM_SMEM);
    cudaFuncSetAttribute(gemm_mma<false>, cudaFuncAttributeMaxDynamicSharedMemorySize, GEMM_SMEM);

    {
        int blocks = (total_heads + 7) / 8;
        prep_q<<<blocks, 256>>>(x, cosb, sinb, ahi, alo, qhi, qlo,
                                0.125f * LOG2E, T, total_heads);
    }
    split_bf16<<<(C * C / 4 + 255) / 256, 256>>>(kv_w, bhi, blo, C * C / 4);
    {
        dim3 grid(C / 128, M / 128);
        gemm_mma<true><<<grid, 256, GEMM_SMEM>>>(ahi, alo, bhi, blo, nullptr,
                                                 cosb, sinb, kvhi, kvlo, M, C, C, T);
    }
    {
        dim3 grid(T / 64, H_HEADS, B);
        attn_mma<<<grid, 256>>>(qhi, qlo, kvhi, kvlo, ahi, alo, wl, T);
    }
    split_bf16<<<(C * C / 4 + 255) / 256, 256>>>(proj_w, bhi, blo, C * C / 4);
    {
        dim3 grid(C / 128, M / 128);
        gemm_mma<false><<<grid, 256, GEMM_SMEM>>>(ahi, alo, bhi, blo, (float*)d_out,
                                                  nullptr, nullptr, nullptr, nullptr, M, C, C, T);
    }
}

// round 12
// speedup vs baseline: 1.5871x; 1.4560x over previous
#include <cuda_runtime.h>
#include <cuda_bf16.h>
#include <cuda_fp16.h>
#include <cstdint>

#define H_HEADS 16
#define DHEAD   64
#define RMS_EPS 1.1920928955078125e-07f
#define MAXTOK  4096
#define LOG2E   1.4426950408889634f
#define FIXMAX  12.0f

// ---------------- scratch ----------------
__device__ __half         g_a16 [MAXTOK * 1024];
__device__ __half         g_b16 [1024 * 1024];
__device__ __nv_bfloat16  g_qhi [MAXTOK * 1024];
__device__ __nv_bfloat16  g_qlo [MAXTOK * 1024];
__device__ __nv_bfloat16  g_kvhi[MAXTOK * 1024];
__device__ __nv_bfloat16  g_kvlo[MAXTOK * 1024];

// ---------------- helpers ----------------
__device__ __forceinline__ uint32_t smem_u32(const void* p) {
    uint32_t a;
    asm("{ .reg .u64 t; cvta.to.shared.u64 t, %1; cvt.u32.u64 %0, t; }" : "=r"(a) : "l"(p));
    return a;
}

#define LDSM_X4(r0, r1, r2, r3, addr) \
    asm volatile("ldmatrix.sync.aligned.m8n8.x4.shared.b16 {%0,%1,%2,%3}, [%4];" \
                 : "=r"(r0), "=r"(r1), "=r"(r2), "=r"(r3) : "r"(addr))

#define LDSM_X4_T(r0, r1, r2, r3, addr) \
    asm volatile("ldmatrix.sync.aligned.m8n8.x4.trans.shared.b16 {%0,%1,%2,%3}, [%4];" \
                 : "=r"(r0), "=r"(r1), "=r"(r2), "=r"(r3) : "r"(addr))

#define MMA_BF16(c0, c1, c2, c3, a0, a1, a2, a3, b0, b1) \
    asm volatile("mma.sync.aligned.m16n8k16.row.col.f32.bf16.bf16.f32 " \
                 "{%0,%1,%2,%3}, {%4,%5,%6,%7}, {%8,%9}, {%0,%1,%2,%3};" \
                 : "+f"(c0), "+f"(c1), "+f"(c2), "+f"(c3) \
                 : "r"(a0), "r"(a1), "r"(a2), "r"(a3), "r"(b0), "r"(b1))

#define MMA_FP16(c0, c1, c2, c3, a0, a1, a2, a3, b0, b1) \
    asm volatile("mma.sync.aligned.m16n8k16.row.col.f32.f16.f16.f32 " \
                 "{%0,%1,%2,%3}, {%4,%5,%6,%7}, {%8,%9}, {%0,%1,%2,%3};" \
                 : "+f"(c0), "+f"(c1), "+f"(c2), "+f"(c3) \
                 : "r"(a0), "r"(a1), "r"(a2), "r"(a3), "r"(b0), "r"(b1))

#define CP16(saddr, gptr) \
    asm volatile("cp.async.cg.shared.global [%0], [%1], 16;" :: "r"(saddr), "l"(gptr))
#define CPA16(saddr, gptr) \
    asm volatile("cp.async.ca.shared.global [%0], [%1], 16;" :: "r"(saddr), "l"(gptr))
#define CP_COMMIT() asm volatile("cp.async.commit_group;" ::: "memory")
#define CP_WAIT1()  asm volatile("cp.async.wait_group 1;" ::: "memory")
#define CP_WAIT0()  asm volatile("cp.async.wait_group 0;" ::: "memory")

__device__ __forceinline__ uint32_t pack_bf2(__nv_bfloat16 a, __nv_bfloat16 b) {
    __nv_bfloat162 t(a, b);
    return *(uint32_t*)&t;
}
__device__ __forceinline__ uint32_t pack_h2(float a, float b) {
    __half2 t(__float2half(a), __float2half(b));
    return *(uint32_t*)&t;
}
__device__ __forceinline__ void split_pack(float x, float y, uint32_t& hi, uint32_t& lo) {
    __nv_bfloat16 hx = __float2bfloat16(x), hy = __float2bfloat16(y);
    __nv_bfloat16 lx = __float2bfloat16(x - __bfloat162float(hx));
    __nv_bfloat16 ly = __float2bfloat16(y - __bfloat162float(hy));
    hi = pack_bf2(hx, hy);
    lo = pack_bf2(lx, ly);
}

// ---------------------------------------------------------------------------
// fp32 -> fp16 convert (weights)
// ---------------------------------------------------------------------------
__global__ __launch_bounds__(256) void to_fp16(
    const float* __restrict__ in, __half* __restrict__ out, int n4)
{
    int i = blockIdx.x * blockDim.x + threadIdx.x;
    if (i >= n4) return;
    float4 v = ((const float4*)in)[i];
    ((uint32_t*)out)[2 * i]     = pack_h2(v.x, v.y);
    ((uint32_t*)out)[2 * i + 1] = pack_h2(v.z, v.w);
}

// ---------------------------------------------------------------------------
// prep_q: x -> fp16 copy [M,C] (GEMM1 A) + roped/rms/scaled q bf16 split
// ---------------------------------------------------------------------------
__global__ __launch_bounds__(256) void prep_q(
    const float* __restrict__ x, const float* __restrict__ cosb,
    const float* __restrict__ sinb,
    __half* __restrict__ a16,
    __nv_bfloat16* __restrict__ qhi, __nv_bfloat16* __restrict__ qlo,
    float qscale, int T, int total_heads)
{
    int w = blockIdx.x * 8 + (threadIdx.x >> 5);
    if (w >= total_heads) return;
    int lane = threadIdx.x & 31;
    int h = w % H_HEADS;
    int t = (w / H_HEADS) % T;
    int b = w / (H_HEADS * T);

    size_t ibase = (size_t)w * DHEAD;
    float x1 = x[ibase + lane];
    float x2 = x[ibase + 32 + lane];

    a16[ibase + lane]      = __float2half(x1);
    a16[ibase + 32 + lane] = __float2half(x2);

    float c  = cosb[t * 32 + lane];
    float s  = sinb[t * 32 + lane];
    float o1 = x1 * c + x2 * s;
    float o2 = -x1 * s + x2 * c;

    float ss = o1 * o1 + o2 * o2;
#pragma unroll
    for (int off = 16; off; off >>= 1)
        ss += __shfl_xor_sync(0xffffffffu, ss, off);
    float r = rsqrtf(ss * (1.0f / 64.0f) + RMS_EPS) * qscale;

    o1 *= r; o2 *= r;
    __nv_bfloat16 h1 = __float2bfloat16(o1);
    __nv_bfloat16 h2 = __float2bfloat16(o2);
    size_t obase = ((size_t)(b * H_HEADS + h) * T + t) * DHEAD;
    qhi[obase + lane]      = h1;
    qhi[obase + 32 + lane] = h2;
    qlo[obase + lane]      = __float2bfloat16(o1 - __bfloat162float(h1));
    qlo[obase + 32 + lane] = __float2bfloat16(o2 - __bfloat162float(h2));
}

// ---------------------------------------------------------------------------
// cp.async double-buffered fp16 NT GEMM (single term).
// ---------------------------------------------------------------------------
#define KCH2   32
#define ROWB2  80
#define MATB2  (128 * ROWB2)   // 10240
#define STB2   (2 * MATB2)     // 20480 per stage
#define GEMM_SMEM (2 * STB2)   // 40960

template <bool FUSE_ROPE>
__global__ __launch_bounds__(256, 2) void gemm_mma(
    const __half* __restrict__ A, const __half* __restrict__ B,
    float* __restrict__ C,
    const float* __restrict__ cosb, const float* __restrict__ sinb,
    __nv_bfloat16* __restrict__ Ohi, __nv_bfloat16* __restrict__ Olo,
    int M, int N, int K, int T)
{
    extern __shared__ char smem[];
    const uint32_t sb = smem_u32(smem);

    const int tid  = threadIdx.x;
    const int wid  = tid >> 5;
    const int lane = tid & 31;
    const int m0 = blockIdx.y * 128, n0 = blockIdx.x * 128;

    const int wm = (wid & 3) * 32;
    const int wn = (wid >> 2) * 64;

    const int a_row = (lane & 7) + (lane & 8);
    const int a_col = (lane >> 4) * 16;
    const int b_row = (lane & 7) + ((lane >> 4) & 1) * 8;
    const int b_col = ((lane >> 3) & 1) * 16;

    const int grow = tid >> 1;
    const uint32_t s_off = (uint32_t)grow * ROWB2 + (tid & 1) * 32;
    const int gelem = (tid & 1) * 16;

    const __half* gA = A + (size_t)(m0 + grow) * K + gelem;
    const __half* gB = B + (size_t)(n0 + grow) * K + gelem;

    float c[2][8][4];
#pragma unroll
    for (int i = 0; i < 2; i++)
#pragma unroll
        for (int j = 0; j < 8; j++)
#pragma unroll
            for (int e = 0; e < 4; e++) c[i][j][e] = 0.f;

    const int nchunk = K / KCH2;

    auto fill = [&](int stage, int ch) {
        const int k0 = ch * KCH2;
        uint32_t s0 = sb + stage * STB2 + s_off;
        const __half* a0 = gA + k0;
        const __half* b0 = gB + k0;
        CP16(s0,         a0);  CP16(s0 + 16,         a0 + 8);
        CP16(s0 + MATB2, b0);  CP16(s0 + MATB2 + 16, b0 + 8);
    };

    fill(0, 0);
    CP_COMMIT();

    for (int ch = 0; ch < nchunk; ch++) {
        const int st = ch & 1;
        if (ch + 1 < nchunk) { fill(st ^ 1, ch + 1); CP_COMMIT(); CP_WAIT1(); }
        else                 { CP_WAIT0(); }
        __syncthreads();

        const uint32_t sA = sb + st * STB2;
        const uint32_t sB = sA + MATB2;

#pragma unroll
        for (int ks = 0; ks < 2; ks++) {
            const int kb = ks * 32;
            uint32_t ah[2][4], bh[4][4];
#pragma unroll
            for (int mi = 0; mi < 2; mi++) {
                uint32_t addr = sA + (uint32_t)(wm + mi * 16 + a_row) * ROWB2 + kb + a_col;
                LDSM_X4(ah[mi][0], ah[mi][1], ah[mi][2], ah[mi][3], addr);
            }
#pragma unroll
            for (int nb = 0; nb < 4; nb++) {
                uint32_t addr = sB + (uint32_t)(wn + nb * 16 + b_row) * ROWB2 + kb + b_col;
                LDSM_X4(bh[nb][0], bh[nb][1], bh[nb][2], bh[nb][3], addr);
            }
#pragma unroll
            for (int mi = 0; mi < 2; mi++)
#pragma unroll
                for (int nb = 0; nb < 4; nb++)
#pragma unroll
                    for (int sj = 0; sj < 2; sj++) {
                        float* cc = c[mi][nb * 2 + sj];
                        MMA_FP16(cc[0], cc[1], cc[2], cc[3],
                                 ah[mi][0], ah[mi][1], ah[mi][2], ah[mi][3],
                                 bh[nb][sj * 2], bh[nb][sj * 2 + 1]);
                    }
        }
        __syncthreads();
    }

    const int g  = lane >> 2;
    const int t2 = (lane & 3) * 2;

    if (!FUSE_ROPE) {
#pragma unroll
        for (int mi = 0; mi < 2; mi++) {
            float* r0 = C + (size_t)(m0 + wm + mi * 16 + g) * N + n0 + wn + t2;
            float* r1 = r0 + 8 * N;
#pragma unroll
            for (int nj = 0; nj < 8; nj++) {
                *(float2*)(r0 + nj * 8) = make_float2(c[mi][nj][0], c[mi][nj][1]);
                *(float2*)(r1 + nj * 8) = make_float2(c[mi][nj][2], c[mi][nj][3]);
            }
        }
    } else {
        const int h = (n0 + wn) >> 6;
#pragma unroll
        for (int mi = 0; mi < 2; mi++) {
#pragma unroll
            for (int half = 0; half < 2; half++) {
                const int m = m0 + wm + mi * 16 + g + half * 8;
                const int b = m / T, t = m % T;
                float o1[4][2], o2[4][2];
                float ss = 0.f;
#pragma unroll
                for (int nj = 0; nj < 4; nj++) {
#pragma unroll
                    for (int e = 0; e < 2; e++) {
                        const int d = nj * 8 + t2 + e;
                        float x1 = c[mi][nj][half * 2 + e];
                        float x2 = c[mi][nj + 4][half * 2 + e];
                        float co = cosb[t * 32 + d];
                        float si = sinb[t * 32 + d];
                        float a = x1 * co + x2 * si;
                        float bb = -x1 * si + x2 * co;
                        o1[nj][e] = a; o2[nj][e] = bb;
                        ss += a * a + bb * bb;
                    }
                }
                ss += __shfl_xor_sync(0xffffffffu, ss, 1);
                ss += __shfl_xor_sync(0xffffffffu, ss, 2);
                float r = rsqrtf(ss * (1.0f / 64.0f) + RMS_EPS);
                const size_t ob = ((size_t)(b * H_HEADS + h) * T + t) * DHEAD + t2;
#pragma unroll
                for (int nj = 0; nj < 4; nj++) {
                    uint32_t hi, lo;
                    split_pack(o1[nj][0] * r, o1[nj][1] * r, hi, lo);
                    *(uint32_t*)(Ohi + ob + nj * 8) = hi;
                    *(uint32_t*)(Olo + ob + nj * 8) = lo;
                    split_pack(o2[nj][0] * r, o2[nj][1] * r, hi, lo);
                    *(uint32_t*)(Ohi + ob + 32 + nj * 8) = hi;
                    *(uint32_t*)(Olo + ob + 32 + nj * 8) = lo;
                }
            }
        }
    }
}

// ---------------------------------------------------------------------------
// Sliding-window attention (R11 structure): 8 warps = 4 m-warps x 2 key-groups,
// cp.async.ca double-buffered KV, fixed-max linear softmax, bf16 3-term.
// Output: fp16 single (proj GEMM A operand).
// ---------------------------------------------------------------------------
#define ATT_ROWB 144
#define ATT_MAT  (64 * ATT_ROWB)
#define ATT_STG  (2 * ATT_MAT)

__global__ __launch_bounds__(256, 2) void attn_mma(
    const __nv_bfloat16* __restrict__ Qhi, const __nv_bfloat16* __restrict__ Qlo,
    const __nv_bfloat16* __restrict__ KVhi, const __nv_bfloat16* __restrict__ KVlo,
    __half* __restrict__ Out,
    const int* __restrict__ wl, int T)
{
    __shared__ char smc[2 * ATT_STG];
    const uint32_t sbase = smem_u32(smc);

    const int tid = threadIdx.x, wid = tid >> 5, lane = tid & 31;
    const int mwarp = wid & 3, kgrp = wid >> 2;
    const int qt = blockIdx.x, h = blockIdx.y, b = blockIdx.z;
    const int q0 = qt * 64;
    const int W = *wl;
    const size_t hb = (size_t)(b * H_HEADS + h) * T * DHEAD;

    const int lrow = tid >> 2;
    const uint32_t s_off = (uint32_t)lrow * ATT_ROWB + (tid & 3) * 32;
    const int gcol = (tid & 3) * 16;

    const int a_row  = (lane & 7) + (lane & 8);
    const int a_colB = (lane >> 4) * 16;
    const int b_row  = (lane & 7) + ((lane >> 4) & 1) * 8;
    const int b_colB = ((lane >> 3) & 1) * 16;
    const int t_m = lane >> 3, t_r = lane & 7;

    auto fill_kv = [&](int st, int k0) {
        uint32_t s0 = sbase + st * ATT_STG + s_off;
        const __nv_bfloat16* gh = KVhi + hb + (size_t)(k0 + lrow) * DHEAD + gcol;
        const __nv_bfloat16* gl = KVlo + hb + (size_t)(k0 + lrow) * DHEAD + gcol;
        CPA16(s0,      gh);  CPA16(s0 + 16,      gh + 8);
        CPA16(s0 + ATT_MAT, gl);  CPA16(s0 + ATT_MAT + 16, gl + 8);
    };

    // stage Q through stage 0 -> fragments
    {
        uint32_t s0 = sbase + s_off;
        const __nv_bfloat16* gh = Qhi + hb + (size_t)(q0 + lrow) * DHEAD + gcol;
        const __nv_bfloat16* gl = Qlo + hb + (size_t)(q0 + lrow) * DHEAD + gcol;
        CPA16(s0,      gh);  CPA16(s0 + 16,      gh + 8);
        CPA16(s0 + ATT_MAT, gl);  CPA16(s0 + ATT_MAT + 16, gl + 8);
        CP_COMMIT();
        CP_WAIT0();
    }
    __syncthreads();
    uint32_t qh[4][4], ql[4][4];
#pragma unroll
    for (int kc = 0; kc < 4; kc++) {
        uint32_t ad = sbase + (uint32_t)(mwarp * 16 + a_row) * ATT_ROWB + kc * 32 + a_colB;
        LDSM_X4(qh[kc][0], qh[kc][1], qh[kc][2], qh[kc][3], ad);
        LDSM_X4(ql[kc][0], ql[kc][1], ql[kc][2], ql[kc][3], ad + ATT_MAT);
    }
    __syncthreads();

    float o[8][4];
#pragma unroll
    for (int i = 0; i < 8; i++)
#pragma unroll
        for (int e = 0; e < 4; e++) o[i][e] = 0.f;
    float lsum[2] = {0.f, 0.f};

    int lo_t = q0 - W; if (lo_t < 0) lo_t = 0;
    const int kt_lo = lo_t >> 6;

    fill_kv(0, kt_lo * 64);
    CP_COMMIT();

    for (int kt = kt_lo; kt <= qt; kt++) {
        const int k0 = kt * 64;
        const int st = (kt - kt_lo) & 1;
        if (kt < qt) { fill_kv(st ^ 1, k0 + 64); CP_COMMIT(); CP_WAIT1(); }
        else         { CP_WAIT0(); }
        __syncthreads();

        const uint32_t sKhi = sbase + st * ATT_STG;
        const bool fullt = (kt < qt) && (q0 + 63 - k0 <= W);

#pragma unroll
        for (int nc = 0; nc < 2; nc++) {
            const int n16 = kgrp * 2 + nc;

            float s[2][4];
#pragma unroll
            for (int sj = 0; sj < 2; sj++)
#pragma unroll
                for (int e = 0; e < 4; e++) s[sj][e] = 0.f;

#pragma unroll
            for (int kc = 0; kc < 4; kc++) {
                uint32_t bh[4], bl[4];
                uint32_t ad = sKhi + (uint32_t)(n16 * 16 + b_row) * ATT_ROWB + kc * 32 + b_colB;
                LDSM_X4(bh[0], bh[1], bh[2], bh[3], ad);
                LDSM_X4(bl[0], bl[1], bl[2], bl[3], ad + ATT_MAT);
                MMA_BF16(s[0][0], s[0][1], s[0][2], s[0][3],
                         qh[kc][0], qh[kc][1], qh[kc][2], qh[kc][3], bh[0], bh[1]);
                MMA_BF16(s[1][0], s[1][1], s[1][2], s[1][3],
                         qh[kc][0], qh[kc][1], qh[kc][2], qh[kc][3], bh[2], bh[3]);
                MMA_BF16(s[0][0], s[0][1], s[0][2], s[0][3],
                         qh[kc][0], qh[kc][1], qh[kc][2], qh[kc][3], bl[0], bl[1]);
                MMA_BF16(s[1][0], s[1][1], s[1][2], s[1][3],
                         qh[kc][0], qh[kc][1], qh[kc][2], qh[kc][3], bl[2], bl[3]);
                MMA_BF16(s[0][0], s[0][1], s[0][2], s[0][3],
                         ql[kc][0], ql[kc][1], ql[kc][2], ql[kc][3], bh[0], bh[1]);
                MMA_BF16(s[1][0], s[1][1], s[1][2], s[1][3],
                         ql[kc][0], ql[kc][1], ql[kc][2], ql[kc][3], bh[2], bh[3]);
            }

            if (!fullt) {
                const int qr = q0 + mwarp * 16 + (lane >> 2);
#pragma unroll
                for (int sj = 0; sj < 2; sj++) {
                    const int kb = k0 + (n16 * 2 + sj) * 8 + (lane & 3) * 2;
#pragma unroll
                    for (int e = 0; e < 4; e++) {
                        int qq = qr + ((e >= 2) ? 8 : 0);
                        int kk = kb + (e & 1);
                        if (kk > qq || qq - kk > W) s[sj][e] = -1e30f;
                    }
                }
            }

            uint32_t ph[4], pl[4];
#pragma unroll
            for (int sj = 0; sj < 2; sj++)
#pragma unroll
                for (int e = 0; e < 4; e++) {
                    float p = exp2f(s[sj][e] - FIXMAX);
                    s[sj][e] = p;
                    lsum[e >> 1] += p;
                }
            split_pack(s[0][0], s[0][1], ph[0], pl[0]);
            split_pack(s[0][2], s[0][3], ph[1], pl[1]);
            split_pack(s[1][0], s[1][1], ph[2], pl[2]);
            split_pack(s[1][2], s[1][3], ph[3], pl[3]);

#pragma unroll
            for (int dg = 0; dg < 4; dg++) {
                uint32_t vh[4], vl[4];
                uint32_t ad = sKhi + (uint32_t)(n16 * 16 + t_r + (t_m & 1) * 8) * ATT_ROWB
                            + dg * 32 + (t_m >> 1) * 16;
                LDSM_X4_T(vh[0], vh[1], vh[2], vh[3], ad);
                LDSM_X4_T(vl[0], vl[1], vl[2], vl[3], ad + ATT_MAT);
                float* c0 = o[dg * 2];
                float* c1 = o[dg * 2 + 1];
                MMA_BF16(c0[0], c0[1], c0[2], c0[3], ph[0], ph[1], ph[2], ph[3], vh[0], vh[1]);
                MMA_BF16(c1[0], c1[1], c1[2], c1[3], ph[0], ph[1], ph[2], ph[3], vh[2], vh[3]);
                MMA_BF16(c0[0], c0[1], c0[2], c0[3], pl[0], pl[1], pl[2], pl[3], vh[0], vh[1]);
                MMA_BF16(c1[0], c1[1], c1[2], c1[3], pl[0], pl[1], pl[2], pl[3], vh[2], vh[3]);
                MMA_BF16(c0[0], c0[1], c0[2], c0[3], ph[0], ph[1], ph[2], ph[3], vl[0], vl[1]);
                MMA_BF16(c1[0], c1[1], c1[2], c1[3], ph[0], ph[1], ph[2], ph[3], vl[2], vl[3]);
            }
        }
        __syncthreads();
    }

    // epilogue: cross-group reduce (linear partials add), fp16 output
    float* red = (float*)smc;
    if (kgrp == 1) {
        float* dst = red + (tid - 128) * 34;
#pragma unroll
        for (int i = 0; i < 8; i++)
#pragma unroll
            for (int e = 0; e < 4; e++) dst[i * 4 + e] = o[i][e];
        dst[32] = lsum[0];
        dst[33] = lsum[1];
    }
    __syncthreads();
    if (kgrp == 0) {
        const float* src = red + tid * 34;
#pragma unroll
        for (int i = 0; i < 8; i++)
#pragma unroll
            for (int e = 0; e < 4; e++) o[i][e] += src[i * 4 + e];
        lsum[0] += src[32];
        lsum[1] += src[33];

        lsum[0] += __shfl_xor_sync(0xffffffffu, lsum[0], 1);
        lsum[0] += __shfl_xor_sync(0xffffffffu, lsum[0], 2);
        lsum[1] += __shfl_xor_sync(0xffffffffu, lsum[1], 1);
        lsum[1] += __shfl_xor_sync(0xffffffffu, lsum[1], 2);
        const float inv0 = 1.f / lsum[0];
        const float inv1 = 1.f / lsum[1];
        const int g = lane >> 2, t2 = (lane & 3) * 2;
        const size_t r0 = (size_t)(b * T + q0 + mwarp * 16 + g) * 1024 + h * 64 + t2;
        const size_t r1 = r0 + (size_t)8 * 1024;
#pragma unroll
        for (int nj = 0; nj < 8; nj++) {
            *(uint32_t*)(Out + r0 + nj * 8) = pack_h2(o[nj][0] * inv0, o[nj][1] * inv0);
            *(uint32_t*)(Out + r1 + nj * 8) = pack_h2(o[nj][2] * inv1, o[nj][3] * inv1);
        }
    }
}

// ---------------------------------------------------------------------------
extern "C" void kernel_launch(void* const* d_in, const int* in_sizes, int n_in,
                              void* d_out, int out_size)
{
    const float* x      = (const float*)d_in[0];
    const float* cosb   = (const float*)d_in[1];
    const float* sinb   = (const float*)d_in[2];
    const float* kv_w   = (const float*)d_in[3];
    const float* proj_w = (const float*)d_in[4];
    const int* wl       = (n_in >= 6) ? (const int*)d_in[5] : nullptr;

    const int T = in_sizes[1] / 32;
    const int C = 1024;
    const int B = in_sizes[0] / (T * C);
    const int M = B * T;
    const int total_heads = M * H_HEADS;

    __half *a16, *b16;
    __nv_bfloat16 *qhi, *qlo, *kvhi, *kvlo;
    cudaGetSymbolAddress((void**)&a16,  g_a16);
    cudaGetSymbolAddress((void**)&b16,  g_b16);
    cudaGetSymbolAddress((void**)&qhi,  g_qhi);
    cudaGetSymbolAddress((void**)&qlo,  g_qlo);
    cudaGetSymbolAddress((void**)&kvhi, g_kvhi);
    cudaGetSymbolAddress((void**)&kvlo, g_kvlo);

    cudaFuncSetAttribute(gemm_mma<true>,  cudaFuncAttributeMaxDynamicSharedMemorySize, GEMM_SMEM);
    cudaFuncSetAttribute(gemm_mma<false>, cudaFuncAttributeMaxDynamicSharedMemorySize, GEMM_SMEM);

    {
        int blocks = (total_heads + 7) / 8;
        prep_q<<<blocks, 256>>>(x, cosb, sinb, a16, qhi, qlo,
                                0.125f * LOG2E, T, total_heads);
    }
    to_fp16<<<(C * C / 4 + 255) / 256, 256>>>(kv_w, b16, C * C / 4);
    {
        dim3 grid(C / 128, M / 128);
        gemm_mma<true><<<grid, 256, GEMM_SMEM>>>(a16, b16, nullptr,
                                                 cosb, sinb, kvhi, kvlo, M, C, C, T);
    }
    {
        dim3 grid(T / 64, H_HEADS, B);
        attn_mma<<<grid, 256>>>(qhi, qlo, kvhi, kvlo, a16, wl, T);
    }
    to_fp16<<<(C * C / 4 + 255) / 256, 256>>>(proj_w, b16, C * C / 4);
    {
        dim3 grid(C / 128, M / 128);
        gemm_mma<false><<<grid, 256, GEMM_SMEM>>>(a16, b16, (float*)d_out,
                                                  nullptr, nullptr, nullptr, nullptr, M, C, C, T);
    }
}

// round 13
// speedup vs baseline: 2.2539x; 1.4201x over previous
#include <cuda_runtime.h>
#include <cuda_bf16.h>
#include <cuda_fp16.h>
#include <cstdint>

#define H_HEADS 16
#define DHEAD   64
#define RMS_EPS 1.1920928955078125e-07f
#define MAXTOK  4096
#define LOG2E   1.4426950408889634f
#define FIXMAX  12.0f

// ---------------- scratch ----------------
__device__ __half g_a16 [MAXTOK * 1024];
__device__ __half g_b16 [1024 * 1024];
__device__ __half g_q16 [MAXTOK * 1024];
__device__ __half g_kv16[MAXTOK * 1024];

// ---------------- helpers ----------------
__device__ __forceinline__ uint32_t smem_u32(const void* p) {
    uint32_t a;
    asm("{ .reg .u64 t; cvta.to.shared.u64 t, %1; cvt.u32.u64 %0, t; }" : "=r"(a) : "l"(p));
    return a;
}

#define LDSM_X4(r0, r1, r2, r3, addr) \
    asm volatile("ldmatrix.sync.aligned.m8n8.x4.shared.b16 {%0,%1,%2,%3}, [%4];" \
                 : "=r"(r0), "=r"(r1), "=r"(r2), "=r"(r3) : "r"(addr))

#define LDSM_X4_T(r0, r1, r2, r3, addr) \
    asm volatile("ldmatrix.sync.aligned.m8n8.x4.trans.shared.b16 {%0,%1,%2,%3}, [%4];" \
                 : "=r"(r0), "=r"(r1), "=r"(r2), "=r"(r3) : "r"(addr))

#define MMA_FP16(c0, c1, c2, c3, a0, a1, a2, a3, b0, b1) \
    asm volatile("mma.sync.aligned.m16n8k16.row.col.f32.f16.f16.f32 " \
                 "{%0,%1,%2,%3}, {%4,%5,%6,%7}, {%8,%9}, {%0,%1,%2,%3};" \
                 : "+f"(c0), "+f"(c1), "+f"(c2), "+f"(c3) \
                 : "r"(a0), "r"(a1), "r"(a2), "r"(a3), "r"(b0), "r"(b1))

#define CP16(saddr, gptr) \
    asm volatile("cp.async.cg.shared.global [%0], [%1], 16;" :: "r"(saddr), "l"(gptr))
#define CPA16(saddr, gptr) \
    asm volatile("cp.async.ca.shared.global [%0], [%1], 16;" :: "r"(saddr), "l"(gptr))
#define CP_COMMIT() asm volatile("cp.async.commit_group;" ::: "memory")
#define CP_WAIT1()  asm volatile("cp.async.wait_group 1;" ::: "memory")
#define CP_WAIT0()  asm volatile("cp.async.wait_group 0;" ::: "memory")

__device__ __forceinline__ uint32_t pack_h2(float a, float b) {
    __half2 t(__float2half(a), __float2half(b));
    return *(uint32_t*)&t;
}

// ---------------------------------------------------------------------------
// fp32 -> fp16 convert (weights)
// ---------------------------------------------------------------------------
__global__ __launch_bounds__(256) void to_fp16(
    const float* __restrict__ in, __half* __restrict__ out, int n4)
{
    int i = blockIdx.x * blockDim.x + threadIdx.x;
    if (i >= n4) return;
    float4 v = ((const float4*)in)[i];
    ((uint32_t*)out)[2 * i]     = pack_h2(v.x, v.y);
    ((uint32_t*)out)[2 * i + 1] = pack_h2(v.z, v.w);
}

// ---------------------------------------------------------------------------
// prep_q: x -> fp16 copy [M,C] (GEMM1 A) + roped/rms/scaled q fp16 [B,H,T,D]
// ---------------------------------------------------------------------------
__global__ __launch_bounds__(256) void prep_q(
    const float* __restrict__ x, const float* __restrict__ cosb,
    const float* __restrict__ sinb,
    __half* __restrict__ a16, __half* __restrict__ q16,
    float qscale, int T, int total_heads)
{
    int w = blockIdx.x * 8 + (threadIdx.x >> 5);
    if (w >= total_heads) return;
    int lane = threadIdx.x & 31;
    int h = w % H_HEADS;
    int t = (w / H_HEADS) % T;
    int b = w / (H_HEADS * T);

    size_t ibase = (size_t)w * DHEAD;
    float x1 = x[ibase + lane];
    float x2 = x[ibase + 32 + lane];

    a16[ibase + lane]      = __float2half(x1);
    a16[ibase + 32 + lane] = __float2half(x2);

    float c  = cosb[t * 32 + lane];
    float s  = sinb[t * 32 + lane];
    float o1 = x1 * c + x2 * s;
    float o2 = -x1 * s + x2 * c;

    float ss = o1 * o1 + o2 * o2;
#pragma unroll
    for (int off = 16; off; off >>= 1)
        ss += __shfl_xor_sync(0xffffffffu, ss, off);
    float r = rsqrtf(ss * (1.0f / 64.0f) + RMS_EPS) * qscale;

    size_t obase = ((size_t)(b * H_HEADS + h) * T + t) * DHEAD;
    q16[obase + lane]      = __float2half(o1 * r);
    q16[obase + 32 + lane] = __float2half(o2 * r);
}

// ---------------------------------------------------------------------------
// cp.async double-buffered fp16 NT GEMM (single term).
// FUSE_ROPE epilogue writes roped+rms fp16 kv [B,H,T,D].
// ---------------------------------------------------------------------------
#define KCH2   32
#define ROWB2  80
#define MATB2  (128 * ROWB2)
#define STB2   (2 * MATB2)
#define GEMM_SMEM (2 * STB2)

template <bool FUSE_ROPE>
__global__ __launch_bounds__(256, 2) void gemm_mma(
    const __half* __restrict__ A, const __half* __restrict__ B,
    float* __restrict__ C,
    const float* __restrict__ cosb, const float* __restrict__ sinb,
    __half* __restrict__ O16,
    int M, int N, int K, int T)
{
    extern __shared__ char smem[];
    const uint32_t sb = smem_u32(smem);

    const int tid  = threadIdx.x;
    const int wid  = tid >> 5;
    const int lane = tid & 31;
    const int m0 = blockIdx.y * 128, n0 = blockIdx.x * 128;

    const int wm = (wid & 3) * 32;
    const int wn = (wid >> 2) * 64;

    const int a_row = (lane & 7) + (lane & 8);
    const int a_col = (lane >> 4) * 16;
    const int b_row = (lane & 7) + ((lane >> 4) & 1) * 8;
    const int b_col = ((lane >> 3) & 1) * 16;

    const int grow = tid >> 1;
    const uint32_t s_off = (uint32_t)grow * ROWB2 + (tid & 1) * 32;
    const int gelem = (tid & 1) * 16;

    const __half* gA = A + (size_t)(m0 + grow) * K + gelem;
    const __half* gB = B + (size_t)(n0 + grow) * K + gelem;

    float c[2][8][4];
#pragma unroll
    for (int i = 0; i < 2; i++)
#pragma unroll
        for (int j = 0; j < 8; j++)
#pragma unroll
            for (int e = 0; e < 4; e++) c[i][j][e] = 0.f;

    const int nchunk = K / KCH2;

    auto fill = [&](int stage, int ch) {
        const int k0 = ch * KCH2;
        uint32_t s0 = sb + stage * STB2 + s_off;
        const __half* a0 = gA + k0;
        const __half* b0 = gB + k0;
        CP16(s0,         a0);  CP16(s0 + 16,         a0 + 8);
        CP16(s0 + MATB2, b0);  CP16(s0 + MATB2 + 16, b0 + 8);
    };

    fill(0, 0);
    CP_COMMIT();

    for (int ch = 0; ch < nchunk; ch++) {
        const int st = ch & 1;
        if (ch + 1 < nchunk) { fill(st ^ 1, ch + 1); CP_COMMIT(); CP_WAIT1(); }
        else                 { CP_WAIT0(); }
        __syncthreads();

        const uint32_t sA = sb + st * STB2;
        const uint32_t sB = sA + MATB2;

#pragma unroll
        for (int ks = 0; ks < 2; ks++) {
            const int kb = ks * 32;
            uint32_t ah[2][4], bh[4][4];
#pragma unroll
            for (int mi = 0; mi < 2; mi++) {
                uint32_t addr = sA + (uint32_t)(wm + mi * 16 + a_row) * ROWB2 + kb + a_col;
                LDSM_X4(ah[mi][0], ah[mi][1], ah[mi][2], ah[mi][3], addr);
            }
#pragma unroll
            for (int nb = 0; nb < 4; nb++) {
                uint32_t addr = sB + (uint32_t)(wn + nb * 16 + b_row) * ROWB2 + kb + b_col;
                LDSM_X4(bh[nb][0], bh[nb][1], bh[nb][2], bh[nb][3], addr);
            }
#pragma unroll
            for (int mi = 0; mi < 2; mi++)
#pragma unroll
                for (int nb = 0; nb < 4; nb++)
#pragma unroll
                    for (int sj = 0; sj < 2; sj++) {
                        float* cc = c[mi][nb * 2 + sj];
                        MMA_FP16(cc[0], cc[1], cc[2], cc[3],
                                 ah[mi][0], ah[mi][1], ah[mi][2], ah[mi][3],
                                 bh[nb][sj * 2], bh[nb][sj * 2 + 1]);
                    }
        }
        __syncthreads();
    }

    const int g  = lane >> 2;
    const int t2 = (lane & 3) * 2;

    if (!FUSE_ROPE) {
#pragma unroll
        for (int mi = 0; mi < 2; mi++) {
            float* r0 = C + (size_t)(m0 + wm + mi * 16 + g) * N + n0 + wn + t2;
            float* r1 = r0 + 8 * N;
#pragma unroll
            for (int nj = 0; nj < 8; nj++) {
                *(float2*)(r0 + nj * 8) = make_float2(c[mi][nj][0], c[mi][nj][1]);
                *(float2*)(r1 + nj * 8) = make_float2(c[mi][nj][2], c[mi][nj][3]);
            }
        }
    } else {
        const int h = (n0 + wn) >> 6;
#pragma unroll
        for (int mi = 0; mi < 2; mi++) {
#pragma unroll
            for (int half = 0; half < 2; half++) {
                const int m = m0 + wm + mi * 16 + g + half * 8;
                const int b = m / T, t = m % T;
                float o1[4][2], o2[4][2];
                float ss = 0.f;
#pragma unroll
                for (int nj = 0; nj < 4; nj++) {
#pragma unroll
                    for (int e = 0; e < 2; e++) {
                        const int d = nj * 8 + t2 + e;
                        float x1 = c[mi][nj][half * 2 + e];
                        float x2 = c[mi][nj + 4][half * 2 + e];
                        float co = cosb[t * 32 + d];
                        float si = sinb[t * 32 + d];
                        float a = x1 * co + x2 * si;
                        float bb = -x1 * si + x2 * co;
                        o1[nj][e] = a; o2[nj][e] = bb;
                        ss += a * a + bb * bb;
                    }
                }
                ss += __shfl_xor_sync(0xffffffffu, ss, 1);
                ss += __shfl_xor_sync(0xffffffffu, ss, 2);
                float r = rsqrtf(ss * (1.0f / 64.0f) + RMS_EPS);
                const size_t ob = ((size_t)(b * H_HEADS + h) * T + t) * DHEAD + t2;
#pragma unroll
                for (int nj = 0; nj < 4; nj++) {
                    *(uint32_t*)(O16 + ob + nj * 8)      = pack_h2(o1[nj][0] * r, o1[nj][1] * r);
                    *(uint32_t*)(O16 + ob + 32 + nj * 8) = pack_h2(o2[nj][0] * r, o2[nj][1] * r);
                }
            }
        }
    }
}

// ---------------------------------------------------------------------------
// Sliding-window attention, full fp16 single-term:
// 8 warps = 4 m-warps x 2 key-groups, cp.async.ca double-buffered KV,
// fixed-max linear softmax. Output fp16 (proj GEMM A operand).
// ---------------------------------------------------------------------------
#define ATT_ROWB 144
#define ATT_MAT  (64 * ATT_ROWB)     // one fp16 64x64 matrix (128B rows + pad)

__global__ __launch_bounds__(256, 3) void attn_mma(
    const __half* __restrict__ Q16, const __half* __restrict__ KV16,
    __half* __restrict__ Out,
    const int* __restrict__ wl, int T)
{
    __shared__ char smc[2 * ATT_MAT];   // 18432 B: 2 KV stages; reused for reduce
    const uint32_t sbase = smem_u32(smc);

    const int tid = threadIdx.x, wid = tid >> 5, lane = tid & 31;
    const int mwarp = wid & 3, kgrp = wid >> 2;
    const int qt = blockIdx.x, h = blockIdx.y, b = blockIdx.z;
    const int q0 = qt * 64;
    const int W = *wl;
    const size_t hb = (size_t)(b * H_HEADS + h) * T * DHEAD;

    // staging: 256 threads x 32B cover 64 rows x 128B
    const int lrow = tid >> 2;
    const uint32_t s_off = (uint32_t)lrow * ATT_ROWB + (tid & 3) * 32;
    const int gcol = (tid & 3) * 16;

    const int a_row  = (lane & 7) + (lane & 8);
    const int a_colB = (lane >> 4) * 16;
    const int b_row  = (lane & 7) + ((lane >> 4) & 1) * 8;
    const int b_colB = ((lane >> 3) & 1) * 16;
    const int t_m = lane >> 3, t_r = lane & 7;

    auto fill_kv = [&](int st, int k0) {
        uint32_t s0 = sbase + st * ATT_MAT + s_off;
        const __half* gk = KV16 + hb + (size_t)(k0 + lrow) * DHEAD + gcol;
        CPA16(s0, gk);  CPA16(s0 + 16, gk + 8);
    };

    // stage Q through stage 0 -> fragments
    {
        uint32_t s0 = sbase + s_off;
        const __half* gq = Q16 + hb + (size_t)(q0 + lrow) * DHEAD + gcol;
        CPA16(s0, gq);  CPA16(s0 + 16, gq + 8);
        CP_COMMIT();
        CP_WAIT0();
    }
    __syncthreads();
    uint32_t qf[4][4];
#pragma unroll
    for (int kc = 0; kc < 4; kc++) {
        uint32_t ad = sbase + (uint32_t)(mwarp * 16 + a_row) * ATT_ROWB + kc * 32 + a_colB;
        LDSM_X4(qf[kc][0], qf[kc][1], qf[kc][2], qf[kc][3], ad);
    }
    __syncthreads();

    float o[8][4];
#pragma unroll
    for (int i = 0; i < 8; i++)
#pragma unroll
        for (int e = 0; e < 4; e++) o[i][e] = 0.f;
    float lsum[2] = {0.f, 0.f};

    int lo_t = q0 - W; if (lo_t < 0) lo_t = 0;
    const int kt_lo = lo_t >> 6;

    fill_kv(0, kt_lo * 64);
    CP_COMMIT();

    for (int kt = kt_lo; kt <= qt; kt++) {
        const int k0 = kt * 64;
        const int st = (kt - kt_lo) & 1;
        if (kt < qt) { fill_kv(st ^ 1, k0 + 64); CP_COMMIT(); CP_WAIT1(); }
        else         { CP_WAIT0(); }
        __syncthreads();

        const uint32_t sK = sbase + st * ATT_MAT;
        const bool fullt = (kt < qt) && (q0 + 63 - k0 <= W);

#pragma unroll
        for (int nc = 0; nc < 2; nc++) {
            const int n16 = kgrp * 2 + nc;

            float s[2][4];
#pragma unroll
            for (int sj = 0; sj < 2; sj++)
#pragma unroll
                for (int e = 0; e < 4; e++) s[sj][e] = 0.f;

#pragma unroll
            for (int kc = 0; kc < 4; kc++) {
                uint32_t bf[4];
                uint32_t ad = sK + (uint32_t)(n16 * 16 + b_row) * ATT_ROWB + kc * 32 + b_colB;
                LDSM_X4(bf[0], bf[1], bf[2], bf[3], ad);
                MMA_FP16(s[0][0], s[0][1], s[0][2], s[0][3],
                         qf[kc][0], qf[kc][1], qf[kc][2], qf[kc][3], bf[0], bf[1]);
                MMA_FP16(s[1][0], s[1][1], s[1][2], s[1][3],
                         qf[kc][0], qf[kc][1], qf[kc][2], qf[kc][3], bf[2], bf[3]);
            }

            if (!fullt) {
                const int qr = q0 + mwarp * 16 + (lane >> 2);
#pragma unroll
                for (int sj = 0; sj < 2; sj++) {
                    const int kb = k0 + (n16 * 2 + sj) * 8 + (lane & 3) * 2;
#pragma unroll
                    for (int e = 0; e < 4; e++) {
                        int qq = qr + ((e >= 2) ? 8 : 0);
                        int kk = kb + (e & 1);
                        if (kk > qq || qq - kk > W) s[sj][e] = -1e30f;
                    }
                }
            }

            uint32_t pf[4];
#pragma unroll
            for (int sj = 0; sj < 2; sj++)
#pragma unroll
                for (int e = 0; e < 4; e++) {
                    float p = exp2f(s[sj][e] - FIXMAX);
                    s[sj][e] = p;
                    lsum[e >> 1] += p;
                }
            pf[0] = pack_h2(s[0][0], s[0][1]);
            pf[1] = pack_h2(s[0][2], s[0][3]);
            pf[2] = pack_h2(s[1][0], s[1][1]);
            pf[3] = pack_h2(s[1][2], s[1][3]);

#pragma unroll
            for (int dg = 0; dg < 4; dg++) {
                uint32_t vf[4];
                uint32_t ad = sK + (uint32_t)(n16 * 16 + t_r + (t_m & 1) * 8) * ATT_ROWB
                            + dg * 32 + (t_m >> 1) * 16;
                LDSM_X4_T(vf[0], vf[1], vf[2], vf[3], ad);
                float* c0 = o[dg * 2];
                float* c1 = o[dg * 2 + 1];
                MMA_FP16(c0[0], c0[1], c0[2], c0[3], pf[0], pf[1], pf[2], pf[3], vf[0], vf[1]);
                MMA_FP16(c1[0], c1[1], c1[2], c1[3], pf[0], pf[1], pf[2], pf[3], vf[2], vf[3]);
            }
        }
        __syncthreads();
    }

    // epilogue: cross-group reduce via smem (linear partials add), fp16 out
    float* red = (float*)smc;
    if (kgrp == 1) {
        float* dst = red + (tid - 128) * 34;
#pragma unroll
        for (int i = 0; i < 8; i++)
#pragma unroll
            for (int e = 0; e < 4; e++) dst[i * 4 + e] = o[i][e];
        dst[32] = lsum[0];
        dst[33] = lsum[1];
    }
    __syncthreads();
    if (kgrp == 0) {
        const float* src = red + tid * 34;
#pragma unroll
        for (int i = 0; i < 8; i++)
#pragma unroll
            for (int e = 0; e < 4; e++) o[i][e] += src[i * 4 + e];
        lsum[0] += src[32];
        lsum[1] += src[33];

        lsum[0] += __shfl_xor_sync(0xffffffffu, lsum[0], 1);
        lsum[0] += __shfl_xor_sync(0xffffffffu, lsum[0], 2);
        lsum[1] += __shfl_xor_sync(0xffffffffu, lsum[1], 1);
        lsum[1] += __shfl_xor_sync(0xffffffffu, lsum[1], 2);
        const float inv0 = 1.f / lsum[0];
        const float inv1 = 1.f / lsum[1];
        const int g = lane >> 2, t2 = (lane & 3) * 2;
        const size_t r0 = (size_t)(b * T + q0 + mwarp * 16 + g) * 1024 + h * 64 + t2;
        const size_t r1 = r0 + (size_t)8 * 1024;
#pragma unroll
        for (int nj = 0; nj < 8; nj++) {
            *(uint32_t*)(Out + r0 + nj * 8) = pack_h2(o[nj][0] * inv0, o[nj][1] * inv0);
            *(uint32_t*)(Out + r1 + nj * 8) = pack_h2(o[nj][2] * inv1, o[nj][3] * inv1);
        }
    }
}

// ---------------------------------------------------------------------------
extern "C" void kernel_launch(void* const* d_in, const int* in_sizes, int n_in,
                              void* d_out, int out_size)
{
    const float* x      = (const float*)d_in[0];
    const float* cosb   = (const float*)d_in[1];
    const float* sinb   = (const float*)d_in[2];
    const float* kv_w   = (const float*)d_in[3];
    const float* proj_w = (const float*)d_in[4];
    const int* wl       = (n_in >= 6) ? (const int*)d_in[5] : nullptr;

    const int T = in_sizes[1] / 32;
    const int C = 1024;
    const int B = in_sizes[0] / (T * C);
    const int M = B * T;
    const int total_heads = M * H_HEADS;

    __half *a16, *b16, *q16, *kv16;
    cudaGetSymbolAddress((void**)&a16,  g_a16);
    cudaGetSymbolAddress((void**)&b16,  g_b16);
    cudaGetSymbolAddress((void**)&q16,  g_q16);
    cudaGetSymbolAddress((void**)&kv16, g_kv16);

    cudaFuncSetAttribute(gemm_mma<true>,  cudaFuncAttributeMaxDynamicSharedMemorySize, GEMM_SMEM);
    cudaFuncSetAttribute(gemm_mma<false>, cudaFuncAttributeMaxDynamicSharedMemorySize, GEMM_SMEM);

    {
        int blocks = (total_heads + 7) / 8;
        prep_q<<<blocks, 256>>>(x, cosb, sinb, a16, q16,
                                0.125f * LOG2E, T, total_heads);
    }
    to_fp16<<<(C * C / 4 + 255) / 256, 256>>>(kv_w, b16, C * C / 4);
    {
        dim3 grid(C / 128, M / 128);
        gemm_mma<true><<<grid, 256, GEMM_SMEM>>>(a16, b16, nullptr,
                                                 cosb, sinb, kv16, M, C, C, T);
    }
    {
        dim3 grid(T / 64, H_HEADS, B);
        attn_mma<<<grid, 256>>>(q16, kv16, a16, wl, T);
    }
    to_fp16<<<(C * C / 4 + 255) / 256, 256>>>(proj_w, b16, C * C / 4);
    {
        dim3 grid(C / 128, M / 128);
        gemm_mma<false><<<grid, 256, GEMM_SMEM>>>(a16, b16, (float*)d_out,
                                                  nullptr, nullptr, nullptr, M, C, C, T);
    }
}